// round 11
// baseline (speedup 1.0000x reference)
#include <cuda_runtime.h>

// Problem dims
#define U_LEN 2048
#define R_LEN 256
#define L_LEN 1024
#define M_LEN 512
#define D_DIM 1024
#define NHEAD 16
#define HDIM  64
#define QLEN  (U_LEN + R_LEN)                   // 2304
#define KVLEN (M_LEN + R_LEN + L_LEN + U_LEN)   // 3840
#define MR    (M_LEN + R_LEN)                   // 768
#define KVIN  (MR + U_LEN)                      // 2816

// A tile: 128 rows x 16 k (+4 pad) = 2560 words = 10240 B (unchanged R8)
#define BLKW   2560
#define TILEB  10240
// B tile: 128 rows x 16 k pair-packed, stride 24 -> 3072 words = 12288 B
#define BTW    3072
#define BTILEB 12288
#define NKT    (D_DIM / 16)      // 64 k-tiles

// head-major K: row stride 72 words, col pairs (c,c+4) packed
// head-major V: per 64-row tile, column-major: c*72 + rowpair*2 + half
#define KV_STR  72
#define KTILE_F (64 * KV_STR)        // 4608
#define VTILE_F (64 * KV_STR)        // 4608
#define KHEAD_W (KVLEN * KV_STR)     // 276480
#define VHEAD_W (KVLEN * KV_STR)     // 276480

// log2(e) folded into q scaling: scores arrive in log2 domain
#define QSCALE (0.125f * 1.4426950408889634f)

// Scratch (no cudaMalloc allowed)
__device__ unsigned g_kvin_blk[22 * 64 * BLKW];
__device__ unsigned g_attn_blk[18 * 64 * BLKW];
__device__ unsigned g_Wq_blk  [ 8 * 64 * BTW];
__device__ unsigned g_Wkv_blk [16 * 64 * BTW];
__device__ unsigned g_Wo_blk  [ 8 * 64 * BTW];
__device__ unsigned g_query_t [QLEN * D_DIM];        // pre-scaled tf32 query
__device__ float    g_key_hs  [NHEAD * KHEAD_W];
__device__ float    g_val_hs  [NHEAD * VHEAD_W];

// ---------------------------------------------------------------------------
// helpers
// ---------------------------------------------------------------------------
__device__ __forceinline__ unsigned f2tf32(float f) {
    unsigned r;
    asm("cvt.rna.tf32.f32 %0, %1;" : "=r"(r) : "f"(f));
    return r;
}

__device__ __forceinline__ void mma_tf32(float* d, const unsigned* a, unsigned b0, unsigned b1) {
    asm volatile(
        "mma.sync.aligned.m16n8k8.row.col.f32.tf32.tf32.f32 "
        "{%0,%1,%2,%3}, {%4,%5,%6,%7}, {%8,%9}, {%0,%1,%2,%3};"
        : "+f"(d[0]), "+f"(d[1]), "+f"(d[2]), "+f"(d[3])
        : "r"(a[0]), "r"(a[1]), "r"(a[2]), "r"(a[3]), "r"(b0), "r"(b1));
}

__device__ __forceinline__ unsigned smaddr(const void* p) {
    return (unsigned)__cvta_generic_to_shared(p);
}
__device__ __forceinline__ void mbar_init(unsigned a) {
    asm volatile("mbarrier.init.shared.b64 [%0], 1;" :: "r"(a) : "memory");
}
__device__ __forceinline__ void mbar_expect(unsigned a, unsigned tx) {
    asm volatile("mbarrier.arrive.expect_tx.shared.b64 _, [%0], %1;" :: "r"(a), "r"(tx) : "memory");
}
__device__ __forceinline__ void bulk_g2s(unsigned sdst, const void* gsrc, unsigned bytes, unsigned mbar) {
    asm volatile("cp.async.bulk.shared::cta.global.mbarrier::complete_tx::bytes [%0], [%1], %2, [%3];"
                 :: "r"(sdst), "l"(gsrc), "r"(bytes), "r"(mbar) : "memory");
}
__device__ __forceinline__ void mbar_wait(unsigned a, unsigned ph) {
    asm volatile(
        "{\n\t.reg .pred P;\n\t"
        "WL%=:\n\t"
        "mbarrier.try_wait.parity.acquire.cta.shared::cta.b64 P, [%0], %1, 0x989680;\n\t"
        "@P bra WD%=;\n\t"
        "bra WL%=;\n\t"
        "WD%=:\n\t}"
        :: "r"(a), "r"(ph) : "memory");
}

// pair-pack index helpers: pair p holds (c, c+4); p = (c>>3)*4 + (c&3), q = (c>>2)&1
__device__ __forceinline__ int pk_p(int c) { return ((c >> 3) << 2) + (c & 3); }
__device__ __forceinline__ int pk_q(int c) { return (c >> 2) & 1; }
// V rowpair: rp holds (j, j+4); rp = (j>>3)*4 + (j&3), h = (j>>2)&1
__device__ __forceinline__ int v_rp(int j) { return ((j >> 3) << 2) + (j & 3); }
__device__ __forceinline__ int v_h(int j)  { return (j >> 2) & 1; }

// ---------------------------------------------------------------------------
// Prepass: weights -> pair-packed B tiles (stride 24)
// ---------------------------------------------------------------------------
__global__ void conv_w_blk(const float* __restrict__ src, unsigned* __restrict__ dst, int n4)
{
    int i = blockIdx.x * blockDim.x + threadIdx.x;
    for (; i < n4; i += gridDim.x * blockDim.x) {
        int row = i >> 8;
        int col = (i & 255) * 4;
        float4 v = ((const float4*)src)[i];
        int c0 = col & 15;                         // 0,4,8,12
        int q = pk_q(c0);
        int p0 = (c0 >> 3) * 4;                    // c&3 runs 0..3
        unsigned* base = dst + ((size_t)((row >> 7) * 64 + (col >> 4))) * BTW
                       + (row & 127) * 24 + q;
        base[(p0 + 0) * 2] = f2tf32(v.x);
        base[(p0 + 1) * 2] = f2tf32(v.y);
        base[(p0 + 2) * 2] = f2tf32(v.z);
        base[(p0 + 3) * 2] = f2tf32(v.w);
    }
}

// Prepass: gather concat(mem, rctx, utter) -> blocked A tiles (unchanged layout)
__global__ void conv_kvin_blk(const float* __restrict__ utter,
                              const float* __restrict__ rctx,
                              const float* __restrict__ mem)
{
    int i = blockIdx.x * blockDim.x + threadIdx.x;
    const int n4 = KVIN * D_DIM / 4;
    for (; i < n4; i += gridDim.x * blockDim.x) {
        int row = i >> 8;
        int col = (i & 255) * 4;
        const float4* s = (row < M_LEN)
            ? (const float4*)(mem + (size_t)row * D_DIM + col)
            : (row < MR)
            ? (const float4*)(rctx + (size_t)(row - M_LEN) * D_DIM + col)
            : (const float4*)(utter + (size_t)(row - MR) * D_DIM + col);
        float4 v = *s;
        uint4 o;
        o.x = f2tf32(v.x); o.y = f2tf32(v.y); o.z = f2tf32(v.z); o.w = f2tf32(v.w);
        size_t off = ((size_t)(row >> 7) * 64 + (col >> 4)) * BLKW + (row & 127) * 20 + (col & 15);
        *(uint4*)(g_kvin_blk + off) = o;
    }
}

// Prepass: left-context rows into packed head-major K/V
__global__ void conv_lc(const float* __restrict__ lck, const float* __restrict__ lcv)
{
    int i = blockIdx.x * blockDim.x + threadIdx.x;
    const int n4 = L_LEN * D_DIM / 4;
    for (; i < n4; i += gridDim.x * blockDim.x) {
        int row = i >> 8;
        int col = (i & 255) * 4;
        int head = col >> 6, c0 = col & 63;        // c0 in {0,4,...,60}
        int krow = MR + row;
        float4 k4 = *(const float4*)(lck + (size_t)row * D_DIM + col);
        float4 v4 = *(const float4*)(lcv + (size_t)row * D_DIM + col);
        // K: row-major stride 72, pair-packed columns
        {
            int q = pk_q(c0);
            int p0 = (c0 >> 3) * 4;
            float* base = g_key_hs + (size_t)head * KHEAD_W + (size_t)krow * KV_STR + q;
            base[(p0 + 0) * 2] = k4.x;
            base[(p0 + 1) * 2] = k4.y;
            base[(p0 + 2) * 2] = k4.z;
            base[(p0 + 3) * 2] = k4.w;
        }
        // V: per 64-row tile, column-major (c*72 + rp*2 + h)
        {
            int tile = krow >> 6, j = krow & 63;
            float* base = g_val_hs + (size_t)head * VHEAD_W + (size_t)tile * VTILE_F
                        + v_rp(j) * 2 + v_h(j);
            base[(c0 + 0) * KV_STR] = v4.x;
            base[(c0 + 1) * KV_STR] = v4.y;
            base[(c0 + 2) * KV_STR] = v4.z;
            base[(c0 + 3) * KV_STR] = v4.w;
        }
    }
}

// ---------------------------------------------------------------------------
// TF32 GEMM with bulk-copy pipeline: C = A_blk @ W_blk^T + bias
// BM=BN=128, BK=16, 256 threads (8 warps 4x2), 4-stage, sync per 2 k-tiles.
// B fragments are single LDS.64 (pair-packed, conflict-free).
// ---------------------------------------------------------------------------
#define GEMM_SMEM ((4 * BLKW + 4 * BTW) * 4 + 64)

template <int MODE>
__global__ __launch_bounds__(256, 2)
void gemm_blk(const float* __restrict__ bias,
              float* __restrict__ C0,
              float* __restrict__ C1)
{
    extern __shared__ unsigned gsm[];
    unsigned* As = gsm;               // [4][2560]
    unsigned* Bs = gsm + 4 * BLKW;    // [4][3072]
    const unsigned mb0 = smaddr(gsm + 4 * BLKW + 4 * BTW);

    const int tid  = threadIdx.x;
    const int lane = tid & 31;
    const int warp = tid >> 5;
    const int wr   = warp & 3;
    const int wc   = warp >> 2;
    const int bm = blockIdx.y, bn = blockIdx.x;
    const int tig = lane & 3, grp = lane >> 2;

    const unsigned* Ab =
        (MODE == 0) ? g_kvin_blk + (size_t)(bm + 4) * 64 * BLKW
      : (MODE == 1) ? g_kvin_blk + (size_t)bm * 64 * BLKW
                    : g_attn_blk + (size_t)bm * 64 * BLKW;
    const unsigned* Wb =
        ((MODE == 0) ? g_Wq_blk : (MODE == 1) ? g_Wkv_blk : g_Wo_blk)
        + (size_t)bn * 64 * BTW;

    if (tid == 0) {
        mbar_init(mb0); mbar_init(mb0 + 8); mbar_init(mb0 + 16); mbar_init(mb0 + 24);
    }
    __syncthreads();
    if (tid == 0) {
#pragma unroll
        for (int s = 0; s < 4; s++) {
            mbar_expect(mb0 + 8 * s, TILEB + BTILEB);
            bulk_g2s(smaddr(As + s * BLKW), Ab + (size_t)s * BLKW, TILEB, mb0 + 8 * s);
            bulk_g2s(smaddr(Bs + s * BTW),  Wb + (size_t)s * BTW,  BTILEB, mb0 + 8 * s);
        }
    }

    float acc[2][8][4];
#pragma unroll
    for (int mt = 0; mt < 2; mt++)
#pragma unroll
        for (int nt = 0; nt < 8; nt++)
#pragma unroll
            for (int i = 0; i < 4; i++) acc[mt][nt][i] = 0.f;

    for (int g = 0; g < NKT / 2; g++) {
#pragma unroll
        for (int sub = 0; sub < 2; sub++) {
            const int kt = 2 * g + sub;
            const int s  = kt & 3;
            mbar_wait(mb0 + 8 * s, (unsigned)((kt >> 2) & 1));

            const unsigned* Asl = As + s * BLKW;
            const unsigned* Bsl = Bs + s * BTW;
#pragma unroll
            for (int ks = 0; ks < 2; ks++) {
                int kk = ks * 8;
                unsigned b[8][2];
#pragma unroll
                for (int nt = 0; nt < 8; nt++) {
                    int brow = wc * 64 + nt * 8 + grp;
                    uint2 bb = *(const uint2*)(Bsl + brow * 24 + (ks * 4 + tig) * 2);
                    b[nt][0] = bb.x; b[nt][1] = bb.y;
                }
#pragma unroll
                for (int mt = 0; mt < 2; mt++) {
                    unsigned a[4];
                    int r0 = wr * 32 + mt * 16 + grp;
                    a[0] = Asl[r0 * 20 + kk + tig];       a[1] = Asl[(r0 + 8) * 20 + kk + tig];
                    a[2] = Asl[r0 * 20 + kk + tig + 4];   a[3] = Asl[(r0 + 8) * 20 + kk + tig + 4];
#pragma unroll
                    for (int nt = 0; nt < 8; nt++) mma_tf32(acc[mt][nt], a, b[nt][0], b[nt][1]);
                }
            }
        }
        __syncthreads();
        if (tid == 0 && 2 * g + 4 < NKT) {
#pragma unroll
            for (int sub = 0; sub < 2; sub++) {
                const int kt = 2 * g + 4 + sub;
                const int s  = kt & 3;
                mbar_expect(mb0 + 8 * s, TILEB + BTILEB);
                bulk_g2s(smaddr(As + s * BLKW), Ab + (size_t)kt * BLKW, TILEB, mb0 + 8 * s);
                bulk_g2s(smaddr(Bs + s * BTW),  Wb + (size_t)kt * BTW,  BTILEB, mb0 + 8 * s);
            }
        }
    }

    // epilogue
#pragma unroll
    for (int mt = 0; mt < 2; mt++) {
#pragma unroll
        for (int nt = 0; nt < 8; nt++) {
            int col = bn * 128 + wc * 64 + nt * 8 + 2 * tig;
#pragma unroll
            for (int half = 0; half < 2; half++) {
                int row = bm * 128 + wr * 32 + mt * 16 + grp + half * 8;
                float v0 = acc[mt][nt][half * 2 + 0] + bias[col];
                float v1 = acc[mt][nt][half * 2 + 1] + bias[col + 1];
                if (MODE == 0) {
                    uint2 o = make_uint2(f2tf32(v0 * QSCALE), f2tf32(v1 * QSCALE));
                    *(uint2*)(g_query_t + (size_t)row * D_DIM + col) = o;
                } else if (MODE == 1) {
                    int krow = (row < MR) ? row : row + L_LEN;
                    if (col < D_DIM) {
                        *(float2*)(C0 + (size_t)krow * D_DIM + col) = make_float2(v0, v1);
                        int head = col >> 6, c = col & 63;
                        float* base = g_key_hs + (size_t)head * KHEAD_W
                                    + (size_t)krow * KV_STR + pk_q(c);
                        int p = pk_p(c);
                        base[p * 2] = v0;
                        base[p * 2 + 2] = v1;       // pk_p(c+1) = p+1 (c even)
                    } else {
                        int vc = col - D_DIM;
                        *(float2*)(C1 + (size_t)krow * D_DIM + vc) = make_float2(v0, v1);
                        int head = vc >> 6, c = vc & 63;
                        int tile = krow >> 6, j = krow & 63;
                        float* base = g_val_hs + (size_t)head * VHEAD_W + (size_t)tile * VTILE_F
                                    + v_rp(j) * 2 + v_h(j);
                        base[c * KV_STR] = v0;
                        base[(c + 1) * KV_STR] = v1;
                    }
                } else {
                    *(float2*)(C0 + (size_t)row * D_DIM + col) = make_float2(v0, v1);
                }
            }
        }
    }
}

// ---------------------------------------------------------------------------
// Tensor-core flash attention, 512 threads = 256 q rows of one head.
// 4-stage bulk pipeline, sync per 2 tiles. K/V fragments single LDS.64.
// Softmax in log2 domain.
// ---------------------------------------------------------------------------
#define AT_TK   64
#define AT_NT   (KVLEN / AT_TK)    // 60
#define PS_STR  72
#define ATT_SMEM ((4 * KTILE_F + 4 * VTILE_F + 16 * 16 * PS_STR) * 4 + 64)

__global__ __launch_bounds__(512, 1)
void attn_mma(int dummy)
{
    extern __shared__ float sm[];
    float* Ks = sm;                              // [4][4608]
    float* Vs = sm + 4 * KTILE_F;                // [4][4608]
    float* Pa = sm + 4 * KTILE_F + 4 * VTILE_F;  // [16][16*72]
    const unsigned mb0 = smaddr(Pa + 16 * 16 * PS_STR);

    const int h   = blockIdx.x;
    const int qb  = blockIdx.y;
    const int tid = threadIdx.x;
    const int lane = tid & 31;
    const int w    = tid >> 5;
    const int grp  = lane >> 2;
    const int tig  = lane & 3;
    float* Pw = Pa + w * 16 * PS_STR;

    const float* ksrc = g_key_hs + (size_t)h * KHEAD_W;
    const float* vsrc = g_val_hs + (size_t)h * VHEAD_W;

    if (tid == 0) {
        mbar_init(mb0); mbar_init(mb0 + 8); mbar_init(mb0 + 16); mbar_init(mb0 + 24);
    }
    __syncthreads();
    if (tid == 0) {
#pragma unroll
        for (int s = 0; s < 4; s++) {
            mbar_expect(mb0 + 8 * s, (KTILE_F + VTILE_F) * 4);
            bulk_g2s(smaddr(Ks + s * KTILE_F), ksrc + (size_t)s * KTILE_F, KTILE_F * 4, mb0 + 8 * s);
            bulk_g2s(smaddr(Vs + s * VTILE_F), vsrc + (size_t)s * VTILE_F, VTILE_F * 4, mb0 + 8 * s);
        }
    }

    // Q fragments (pre-scaled tf32, log2 domain)
    unsigned qa[8][4];
    {
        const unsigned* q0 = g_query_t + (size_t)(qb * 256 + w * 16 + grp) * D_DIM + h * HDIM;
        const unsigned* q1 = q0 + 8 * D_DIM;
#pragma unroll
        for (int kb = 0; kb < 8; kb++) {
            qa[kb][0] = q0[kb * 8 + tig];
            qa[kb][1] = q1[kb * 8 + tig];
            qa[kb][2] = q0[kb * 8 + tig + 4];
            qa[kb][3] = q1[kb * 8 + tig + 4];
        }
    }

    float acc[8][4];
#pragma unroll
    for (int nt = 0; nt < 8; nt++)
#pragma unroll
        for (int i = 0; i < 4; i++) acc[nt][i] = 0.f;
    float m0 = -1e30f, m1 = -1e30f, l0 = 0.f, l1 = 0.f;

    for (int g = 0; g < AT_NT / 2; g++) {
#pragma unroll
        for (int sub = 0; sub < 2; sub++) {
            const int t = 2 * g + sub;
            const int s = t & 3;
            mbar_wait(mb0 + 8 * s, (unsigned)((t >> 2) & 1));

            const float* Kc = Ks + s * KTILE_F;
            const float* Vc = Vs + s * VTILE_F;

            // ---- S = Q K^T (log2 domain); K b-frag = 1 LDS.64 ----
            float sc[8][4];
#pragma unroll
            for (int nt = 0; nt < 8; nt++)
#pragma unroll
                for (int i = 0; i < 4; i++) sc[nt][i] = 0.f;
#pragma unroll
            for (int kb = 0; kb < 8; kb++) {
#pragma unroll
                for (int nt = 0; nt < 8; nt++) {
                    uint2 bb = *(const uint2*)(Kc + (nt * 8 + grp) * KV_STR + (kb * 4 + tig) * 2);
                    mma_tf32(sc[nt], qa[kb], bb.x, bb.y);
                }
            }

            // ---- online softmax (exp2) ----
            float mt0 = -1e30f, mt1 = -1e30f;
#pragma unroll
            for (int nt = 0; nt < 8; nt++) {
                mt0 = fmaxf(mt0, fmaxf(sc[nt][0], sc[nt][1]));
                mt1 = fmaxf(mt1, fmaxf(sc[nt][2], sc[nt][3]));
            }
            mt0 = fmaxf(mt0, __shfl_xor_sync(0xffffffff, mt0, 1));
            mt0 = fmaxf(mt0, __shfl_xor_sync(0xffffffff, mt0, 2));
            mt1 = fmaxf(mt1, __shfl_xor_sync(0xffffffff, mt1, 1));
            mt1 = fmaxf(mt1, __shfl_xor_sync(0xffffffff, mt1, 2));

            float mn0 = fmaxf(m0, mt0), mn1 = fmaxf(m1, mt1);
            float c0 = exp2f(m0 - mn0), c1 = exp2f(m1 - mn1);
            l0 *= c0; l1 *= c1;
            m0 = mn0; m1 = mn1;

#pragma unroll
            for (int nt = 0; nt < 8; nt++) {
                float p00 = exp2f(sc[nt][0] - mn0);
                float p01 = exp2f(sc[nt][1] - mn0);
                float p10 = exp2f(sc[nt][2] - mn1);
                float p11 = exp2f(sc[nt][3] - mn1);
                l0 += p00 + p01;
                l1 += p10 + p11;
                *(float2*)&Pw[grp * PS_STR + nt * 8 + 2 * tig]       = make_float2(p00, p01);
                *(float2*)&Pw[(grp + 8) * PS_STR + nt * 8 + 2 * tig] = make_float2(p10, p11);
                acc[nt][0] *= c0; acc[nt][1] *= c0;
                acc[nt][2] *= c1; acc[nt][3] *= c1;
            }
            __syncwarp();

            // ---- acc += P @ V ; V b-frag = 1 LDS.64 ----
#pragma unroll
            for (int kb = 0; kb < 8; kb++) {
                unsigned a[4];
                a[0] = __float_as_uint(Pw[grp * PS_STR + kb * 8 + tig]);
                a[1] = __float_as_uint(Pw[(grp + 8) * PS_STR + kb * 8 + tig]);
                a[2] = __float_as_uint(Pw[grp * PS_STR + kb * 8 + tig + 4]);
                a[3] = __float_as_uint(Pw[(grp + 8) * PS_STR + kb * 8 + tig + 4]);
#pragma unroll
                for (int nt = 0; nt < 8; nt++) {
                    uint2 bb = *(const uint2*)(Vc + (nt * 8 + grp) * KV_STR + (kb * 4 + tig) * 2);
                    mma_tf32(acc[nt], a, bb.x, bb.y);
                }
            }
        }

        __syncthreads();
        if (tid == 0 && 2 * g + 4 < AT_NT) {
#pragma unroll
            for (int sub = 0; sub < 2; sub++) {
                const int t = 2 * g + 4 + sub;
                const int s = t & 3;
                mbar_expect(mb0 + 8 * s, (KTILE_F + VTILE_F) * 4);
                bulk_g2s(smaddr(Ks + s * KTILE_F), ksrc + (size_t)t * KTILE_F, KTILE_F * 4, mb0 + 8 * s);
                bulk_g2s(smaddr(Vs + s * VTILE_F), vsrc + (size_t)t * VTILE_F, VTILE_F * 4, mb0 + 8 * s);
            }
        }
    }

    // ---- finalize: write blocked A layout for gemm2 ----
    l0 += __shfl_xor_sync(0xffffffff, l0, 1);
    l0 += __shfl_xor_sync(0xffffffff, l0, 2);
    l1 += __shfl_xor_sync(0xffffffff, l1, 1);
    l1 += __shfl_xor_sync(0xffffffff, l1, 2);
    float inv0 = 1.f / l0, inv1 = 1.f / l1;

    int r0 = qb * 256 + w * 16 + grp;
    int r1 = r0 + 8;
#pragma unroll
    for (int nt = 0; nt < 8; nt++) {
        int col = h * HDIM + nt * 8 + 2 * tig;
        int kt = col >> 4, c = col & 15;
        size_t o0 = ((size_t)(r0 >> 7) * 64 + kt) * BLKW + (r0 & 127) * 20 + c;
        size_t o1 = ((size_t)(r1 >> 7) * 64 + kt) * BLKW + (r1 & 127) * 20 + c;
        *(uint2*)(g_attn_blk + o0) = make_uint2(f2tf32(acc[nt][0] * inv0), f2tf32(acc[nt][1] * inv0));
        *(uint2*)(g_attn_blk + o1) = make_uint2(f2tf32(acc[nt][2] * inv1), f2tf32(acc[nt][3] * inv1));
    }
}

// ---------------------------------------------------------------------------
extern "C" void kernel_launch(void* const* d_in, const int* in_sizes, int n_in,
                              void* d_out, int out_size)
{
    const float* utter = (const float*)d_in[0];
    const float* rctx  = (const float*)d_in[1];
    const float* mem   = (const float*)d_in[2];
    const float* lck   = (const float*)d_in[3];
    const float* lcv   = (const float*)d_in[4];
    const float* Wq    = (const float*)d_in[5];
    const float* bq    = (const float*)d_in[6];
    const float* Wkv   = (const float*)d_in[7];
    const float* bkv   = (const float*)d_in[8];
    const float* Wo    = (const float*)d_in[9];
    const float* bo    = (const float*)d_in[10];

    float* out = (float*)d_out;                       // [2304, 1024]
    float* key = out + (size_t)QLEN * D_DIM;          // [3840, 1024]
    float* val = key + (size_t)KVLEN * D_DIM;         // [3840, 1024]

    static bool attr_done = false;
    if (!attr_done) {
        cudaFuncSetAttribute(attn_mma, cudaFuncAttributeMaxDynamicSharedMemorySize, ATT_SMEM);
        cudaFuncSetAttribute(gemm_blk<0>, cudaFuncAttributeMaxDynamicSharedMemorySize, GEMM_SMEM);
        cudaFuncSetAttribute(gemm_blk<1>, cudaFuncAttributeMaxDynamicSharedMemorySize, GEMM_SMEM);
        cudaFuncSetAttribute(gemm_blk<2>, cudaFuncAttributeMaxDynamicSharedMemorySize, GEMM_SMEM);
        attr_done = true;
    }

    unsigned *wq_b, *wkv_b, *wo_b;
    cudaGetSymbolAddress((void**)&wq_b,  g_Wq_blk);
    cudaGetSymbolAddress((void**)&wkv_b, g_Wkv_blk);
    cudaGetSymbolAddress((void**)&wo_b,  g_Wo_blk);

    // 0) prepass conversions
    conv_w_blk<<<256, 256>>>(Wq,  wq_b,  D_DIM * D_DIM / 4);
    conv_w_blk<<<512, 256>>>(Wkv, wkv_b, 2 * D_DIM * D_DIM / 4);
    conv_w_blk<<<256, 256>>>(Wo,  wo_b,  D_DIM * D_DIM / 4);
    conv_kvin_blk<<<512, 256>>>(utter, rctx, mem);
    conv_lc<<<256, 256>>>(lck, lcv);

    // 1) query projection -> g_query_t (pre-scaled tf32, log2 domain)
    gemm_blk<0><<<dim3(D_DIM / 128, QLEN / 128), 256, GEMM_SMEM>>>(bq, nullptr, nullptr);

    // 2) kv projection -> key/value (fp32) + packed head-major copies
    gemm_blk<1><<<dim3(2 * D_DIM / 128, KVIN / 128), 256, GEMM_SMEM>>>(bkv, key, val);

    // 3) left-context splice into d_out (contiguous)
    cudaMemcpyAsync(key + (size_t)MR * D_DIM, lck,
                    (size_t)L_LEN * D_DIM * sizeof(float),
                    cudaMemcpyDeviceToDevice, 0);
    cudaMemcpyAsync(val + (size_t)MR * D_DIM, lcv,
                    (size_t)L_LEN * D_DIM * sizeof(float),
                    cudaMemcpyDeviceToDevice, 0);

    // 4) attention -> g_attn_blk (blocked tf32)
    attn_mma<<<dim3(NHEAD, QLEN / 256), 512, ATT_SMEM>>>(0);

    // 5) output projection
    gemm_blk<2><<<dim3(D_DIM / 128, QLEN / 128), 256, GEMM_SMEM>>>(bo, out, nullptr);
}

// round 12
// speedup vs baseline: 1.5373x; 1.5373x over previous
#include <cuda_runtime.h>
#include <cuda_fp16.h>

// Problem dims
#define U_LEN 2048
#define R_LEN 256
#define L_LEN 1024
#define M_LEN 512
#define D_DIM 1024
#define NHEAD 16
#define HDIM  64
#define QLEN  (U_LEN + R_LEN)                   // 2304
#define KVLEN (M_LEN + R_LEN + L_LEN + U_LEN)   // 3840
#define MR    (M_LEN + R_LEN)                   // 768
#define KVIN  (MR + U_LEN)                      // 2816

// GEMM tiles: 128 rows x 16 halves = 1024 words (4KB), XOR swizzle w^(r&7)
#define GT_W 1024
#define GT_B 4096
#define NKT  64

// Attention K / V^T: rows of 64 halves = 32 words + 4 pad = stride 36 words
#define KV_STR   36
#define KTILE_W  (64 * KV_STR)       // 2304 words = 9216 B
#define KHEAD_W  (KVLEN * KV_STR)    // 138240 words
#define NVTILES  (KVLEN / 64)        // 60

// log2(e) folded into q scaling
#define QSCALE (0.125f * 1.4426950408889634f)

// Scratch (no cudaMalloc allowed)
__device__ __align__(16) unsigned g_kvin_h [22 * 64 * GT_W];
__device__ __align__(16) unsigned g_attn_h [18 * 64 * GT_W];
__device__ __align__(16) unsigned g_Wq_h   [ 8 * 64 * GT_W];
__device__ __align__(16) unsigned g_Wkv_h  [16 * 64 * GT_W];
__device__ __align__(16) unsigned g_Wo_h   [ 8 * 64 * GT_W];
__device__ __align__(16) unsigned g_query_h[QLEN * 512];          // fp16 row-major
__device__ __align__(16) unsigned g_key_h  [NHEAD * KHEAD_W];     // [head][row][36w]
__device__ __align__(16) __half   g_val_h  [NHEAD * NVTILES * 64 * 72]; // [head][tile][d][72h]

// ---------------------------------------------------------------------------
// helpers
// ---------------------------------------------------------------------------
__device__ __forceinline__ unsigned f22h2(float a, float b) {
    __half2 h = __floats2half2_rn(a, b);
    return *reinterpret_cast<unsigned*>(&h);
}

__device__ __forceinline__ void mma_f16(float* d, const unsigned* a, unsigned b0, unsigned b1) {
    asm volatile(
        "mma.sync.aligned.m16n8k16.row.col.f32.f16.f16.f32 "
        "{%0,%1,%2,%3}, {%4,%5,%6,%7}, {%8,%9}, {%0,%1,%2,%3};"
        : "+f"(d[0]), "+f"(d[1]), "+f"(d[2]), "+f"(d[3])
        : "r"(a[0]), "r"(a[1]), "r"(a[2]), "r"(a[3]), "r"(b0), "r"(b1));
}

__device__ __forceinline__ unsigned smaddr(const void* p) {
    return (unsigned)__cvta_generic_to_shared(p);
}
__device__ __forceinline__ void mbar_init(unsigned a) {
    asm volatile("mbarrier.init.shared.b64 [%0], 1;" :: "r"(a) : "memory");
}
__device__ __forceinline__ void mbar_expect(unsigned a, unsigned tx) {
    asm volatile("mbarrier.arrive.expect_tx.shared.b64 _, [%0], %1;" :: "r"(a), "r"(tx) : "memory");
}
__device__ __forceinline__ void bulk_g2s(unsigned sdst, const void* gsrc, unsigned bytes, unsigned mbar) {
    asm volatile("cp.async.bulk.shared::cta.global.mbarrier::complete_tx::bytes [%0], [%1], %2, [%3];"
                 :: "r"(sdst), "l"(gsrc), "r"(bytes), "r"(mbar) : "memory");
}
__device__ __forceinline__ void mbar_wait(unsigned a, unsigned ph) {
    asm volatile(
        "{\n\t.reg .pred P;\n\t"
        "WL%=:\n\t"
        "mbarrier.try_wait.parity.acquire.cta.shared::cta.b64 P, [%0], %1, 0x989680;\n\t"
        "@P bra WD%=;\n\t"
        "bra WL%=;\n\t"
        "WD%=:\n\t}"
        :: "r"(a), "r"(ph) : "memory");
}

// ---------------------------------------------------------------------------
// Prepass: weights -> fp16 XOR-swizzled GEMM tiles
// ---------------------------------------------------------------------------
__global__ void conv_w_h(const float* __restrict__ src, unsigned* __restrict__ dst, int n4)
{
    int i = blockIdx.x * blockDim.x + threadIdx.x;
    for (; i < n4; i += gridDim.x * blockDim.x) {
        int row = i >> 8;                // K=1024 -> 256 float4/row
        int col = (i & 255) * 4;
        float4 v = ((const float4*)src)[i];
        unsigned* base = dst + ((size_t)((row >> 7) * 64 + (col >> 4))) * GT_W + (row & 127) * 8;
        int rx = row & 7;
        int w0 = (col & 15) >> 1;        // 0,2,4,6
        base[w0 ^ rx]       = f22h2(v.x, v.y);
        base[(w0 + 1) ^ rx] = f22h2(v.z, v.w);
    }
}

// Prepass: gather concat(mem, rctx, utter) -> fp16 A tiles
__global__ void conv_kvin_h(const float* __restrict__ utter,
                            const float* __restrict__ rctx,
                            const float* __restrict__ mem)
{
    int i = blockIdx.x * blockDim.x + threadIdx.x;
    const int n4 = KVIN * D_DIM / 4;
    for (; i < n4; i += gridDim.x * blockDim.x) {
        int row = i >> 8;
        int col = (i & 255) * 4;
        const float4* s = (row < M_LEN)
            ? (const float4*)(mem + (size_t)row * D_DIM + col)
            : (row < MR)
            ? (const float4*)(rctx + (size_t)(row - M_LEN) * D_DIM + col)
            : (const float4*)(utter + (size_t)(row - MR) * D_DIM + col);
        float4 v = *s;
        unsigned* base = g_kvin_h + ((size_t)((row >> 7) * 64 + (col >> 4))) * GT_W + (row & 127) * 8;
        int rx = row & 7;
        int w0 = (col & 15) >> 1;
        base[w0 ^ rx]       = f22h2(v.x, v.y);
        base[(w0 + 1) ^ rx] = f22h2(v.z, v.w);
    }
}

// Prepass: left-context rows into fp16 K (row-major) and V^T (d-major)
__global__ void conv_lc(const float* __restrict__ lck, const float* __restrict__ lcv)
{
    int i = blockIdx.x * blockDim.x + threadIdx.x;
    const int n4 = L_LEN * D_DIM / 4;
    for (; i < n4; i += gridDim.x * blockDim.x) {
        int row = i >> 8;
        int col = (i & 255) * 4;
        int head = col >> 6, c = col & 63;
        int krow = MR + row;
        float4 k4 = *(const float4*)(lck + (size_t)row * D_DIM + col);
        float4 v4 = *(const float4*)(lcv + (size_t)row * D_DIM + col);
        // K: [head][krow][36w]
        unsigned* kb = g_key_h + ((size_t)head * KVLEN + krow) * KV_STR;
        kb[(c >> 1)]     = f22h2(k4.x, k4.y);
        kb[(c >> 1) + 1] = f22h2(k4.z, k4.w);
        // V^T: [head][tile][d][72h], element j = krow%64
        int tile = krow >> 6, j = krow & 63;
        __half* vb = g_val_h + (((size_t)head * NVTILES + tile) * 64 + c) * 72 + j;
        vb[0]      = __float2half_rn(v4.x);
        vb[72]     = __float2half_rn(v4.y);
        vb[144]    = __float2half_rn(v4.z);
        vb[216]    = __float2half_rn(v4.w);
    }
}

// ---------------------------------------------------------------------------
// FP16 GEMM, bulk-copy 4-stage pipeline: C = A @ W^T + bias
// BM=BN=128, BK=16, 256 threads (8 warps 4x2); m16n8k16 -> 16 MMA/ktile/warp.
// MODE 0: A=kvin blocks 4..21 (q_in) -> g_query_h (fp16, pre-scaled, log2)
// MODE 1: A=kvin blocks 0..21        -> key/value fp32 + fp16 K / V^T
// MODE 2: A=g_attn_h                 -> out fp32
// ---------------------------------------------------------------------------
#define GEMM_SMEM (8 * GT_W * 4 + 64)

template <int MODE>
__global__ __launch_bounds__(256, 2)
void gemm_h(const float* __restrict__ bias,
            float* __restrict__ C0,
            float* __restrict__ C1)
{
    extern __shared__ unsigned gsm[];
    unsigned* As = gsm;               // [4][1024]
    unsigned* Bs = gsm + 4 * GT_W;    // [4][1024]
    const unsigned mb0 = smaddr(gsm + 8 * GT_W);

    const int tid  = threadIdx.x;
    const int lane = tid & 31;
    const int warp = tid >> 5;
    const int wr   = warp & 3;
    const int wc   = warp >> 2;
    const int bm = blockIdx.y, bn = blockIdx.x;
    const int tig = lane & 3, grp = lane >> 2;

    const unsigned* Ab =
        (MODE == 0) ? g_kvin_h + (size_t)(bm + 4) * 64 * GT_W
      : (MODE == 1) ? g_kvin_h + (size_t)bm * 64 * GT_W
                    : g_attn_h + (size_t)bm * 64 * GT_W;
    const unsigned* Wb =
        ((MODE == 0) ? g_Wq_h : (MODE == 1) ? g_Wkv_h : g_Wo_h)
        + (size_t)bn * 64 * GT_W;

    if (tid == 0) {
        mbar_init(mb0); mbar_init(mb0 + 8); mbar_init(mb0 + 16); mbar_init(mb0 + 24);
    }
    __syncthreads();
    if (tid == 0) {
#pragma unroll
        for (int s = 0; s < 4; s++) {
            mbar_expect(mb0 + 8 * s, 2 * GT_B);
            bulk_g2s(smaddr(As + s * GT_W), Ab + (size_t)s * GT_W, GT_B, mb0 + 8 * s);
            bulk_g2s(smaddr(Bs + s * GT_W), Wb + (size_t)s * GT_W, GT_B, mb0 + 8 * s);
        }
    }

    float acc[2][8][4];
#pragma unroll
    for (int mt = 0; mt < 2; mt++)
#pragma unroll
        for (int nt = 0; nt < 8; nt++)
#pragma unroll
            for (int i = 0; i < 4; i++) acc[mt][nt][i] = 0.f;

    const int x0 = tig ^ grp;
    const int x1 = (tig + 4) ^ grp;

    for (int g = 0; g < NKT / 2; g++) {
#pragma unroll
        for (int sub = 0; sub < 2; sub++) {
            const int kt = 2 * g + sub;
            const int s  = kt & 3;
            mbar_wait(mb0 + 8 * s, (unsigned)((kt >> 2) & 1));

            const unsigned* Asl = As + s * GT_W;
            const unsigned* Bsl = Bs + s * GT_W;

            unsigned b[8][2];
#pragma unroll
            for (int nt = 0; nt < 8; nt++) {
                const unsigned* Bp = Bsl + (wc * 64 + nt * 8 + grp) * 8;
                b[nt][0] = Bp[x0];
                b[nt][1] = Bp[x1];
            }
#pragma unroll
            for (int mt = 0; mt < 2; mt++) {
                const unsigned* A0 = Asl + (wr * 32 + mt * 16 + grp) * 8;
                const unsigned* A1 = A0 + 64;
                unsigned a[4];
                a[0] = A0[x0]; a[1] = A1[x0]; a[2] = A0[x1]; a[3] = A1[x1];
#pragma unroll
                for (int nt = 0; nt < 8; nt++) mma_f16(acc[mt][nt], a, b[nt][0], b[nt][1]);
            }
        }
        __syncthreads();
        if (tid == 0 && 2 * g + 4 < NKT) {
#pragma unroll
            for (int sub = 0; sub < 2; sub++) {
                const int kt = 2 * g + 4 + sub;
                const int s  = kt & 3;
                mbar_expect(mb0 + 8 * s, 2 * GT_B);
                bulk_g2s(smaddr(As + s * GT_W), Ab + (size_t)kt * GT_W, GT_B, mb0 + 8 * s);
                bulk_g2s(smaddr(Bs + s * GT_W), Wb + (size_t)kt * GT_W, GT_B, mb0 + 8 * s);
            }
        }
    }

    // epilogue
#pragma unroll
    for (int mt = 0; mt < 2; mt++) {
#pragma unroll
        for (int nt = 0; nt < 8; nt++) {
            int col = bn * 128 + wc * 64 + nt * 8 + 2 * tig;
#pragma unroll
            for (int half = 0; half < 2; half++) {
                int row = bm * 128 + wr * 32 + mt * 16 + grp + half * 8;
                float v0 = acc[mt][nt][half * 2 + 0] + bias[col];
                float v1 = acc[mt][nt][half * 2 + 1] + bias[col + 1];
                if (MODE == 0) {
                    g_query_h[(size_t)row * 512 + (col >> 1)] =
                        f22h2(v0 * QSCALE, v1 * QSCALE);
                } else if (MODE == 1) {
                    int krow = (row < MR) ? row : row + L_LEN;
                    if (col < D_DIM) {
                        *(float2*)(C0 + (size_t)krow * D_DIM + col) = make_float2(v0, v1);
                        int head = col >> 6, c = col & 63;
                        g_key_h[((size_t)head * KVLEN + krow) * KV_STR + (c >> 1)] = f22h2(v0, v1);
                    } else {
                        int vc = col - D_DIM;
                        *(float2*)(C1 + (size_t)krow * D_DIM + vc) = make_float2(v0, v1);
                        int head = vc >> 6, c = vc & 63;
                        int tile = krow >> 6, j = krow & 63;
                        __half* vb = g_val_h + (((size_t)head * NVTILES + tile) * 64 + c) * 72 + j;
                        vb[0]  = __float2half_rn(v0);
                        vb[72] = __float2half_rn(v1);
                    }
                } else {
                    *(float2*)(C0 + (size_t)row * D_DIM + col) = make_float2(v0, v1);
                }
            }
        }
    }
}

// ---------------------------------------------------------------------------
// FP16 tensor-core flash attention, 512 threads = 256 q rows of one head.
// 4-stage bulk pipeline, sync per 2 tiles. m16n8k16; softmax in log2 domain.
// ---------------------------------------------------------------------------
#define AT_NT   NVTILES    // 60
#define PW_STR  36
#define ATT_SMEM ((8 * KTILE_W + 16 * 16 * PW_STR) * 4 + 64)

__global__ __launch_bounds__(512, 1)
void attn_mma(int dummy)
{
    extern __shared__ unsigned sm[];
    unsigned* Ks = sm;                           // [4][2304]
    unsigned* Vs = sm + 4 * KTILE_W;             // [4][2304]
    unsigned* Pa = sm + 8 * KTILE_W;             // [16][16*36]
    const unsigned mb0 = smaddr(Pa + 16 * 16 * PW_STR);

    const int h   = blockIdx.x;
    const int qb  = blockIdx.y;
    const int tid = threadIdx.x;
    const int lane = tid & 31;
    const int w    = tid >> 5;
    const int grp  = lane >> 2;
    const int tig  = lane & 3;
    unsigned* Pw = Pa + w * 16 * PW_STR;

    const unsigned* ksrc = g_key_h + (size_t)h * KHEAD_W;
    const unsigned* vsrc = (const unsigned*)(g_val_h + (size_t)h * NVTILES * 64 * 72);

    if (tid == 0) {
        mbar_init(mb0); mbar_init(mb0 + 8); mbar_init(mb0 + 16); mbar_init(mb0 + 24);
    }
    __syncthreads();
    if (tid == 0) {
#pragma unroll
        for (int s = 0; s < 4; s++) {
            mbar_expect(mb0 + 8 * s, 2 * KTILE_W * 4);
            bulk_g2s(smaddr(Ks + s * KTILE_W), ksrc + (size_t)s * KTILE_W, KTILE_W * 4, mb0 + 8 * s);
            bulk_g2s(smaddr(Vs + s * KTILE_W), vsrc + (size_t)s * KTILE_W, KTILE_W * 4, mb0 + 8 * s);
        }
    }

    // Q fragments (fp16, pre-scaled, log2 domain)
    unsigned qa[4][4];
    {
        const unsigned* q0 = g_query_h + (size_t)(qb * 256 + w * 16 + grp) * 512 + h * 32;
        const unsigned* q1 = q0 + 8 * 512;
#pragma unroll
        for (int kb = 0; kb < 4; kb++) {
            qa[kb][0] = q0[kb * 8 + tig];
            qa[kb][1] = q1[kb * 8 + tig];
            qa[kb][2] = q0[kb * 8 + tig + 4];
            qa[kb][3] = q1[kb * 8 + tig + 4];
        }
    }

    float acc[8][4];
#pragma unroll
    for (int nt = 0; nt < 8; nt++)
#pragma unroll
        for (int i = 0; i < 4; i++) acc[nt][i] = 0.f;
    float m0 = -1e30f, m1 = -1e30f, l0 = 0.f, l1 = 0.f;

    for (int g = 0; g < AT_NT / 2; g++) {
#pragma unroll
        for (int sub = 0; sub < 2; sub++) {
            const int t = 2 * g + sub;
            const int s = t & 3;
            mbar_wait(mb0 + 8 * s, (unsigned)((t >> 2) & 1));

            const unsigned* Kc = Ks + s * KTILE_W;
            const unsigned* Vc = Vs + s * KTILE_W;

            // ---- S = Q K^T (log2 domain) ----
            float sc[8][4];
#pragma unroll
            for (int nt = 0; nt < 8; nt++)
#pragma unroll
                for (int i = 0; i < 4; i++) sc[nt][i] = 0.f;
#pragma unroll
            for (int kb = 0; kb < 4; kb++) {
#pragma unroll
                for (int nt = 0; nt < 8; nt++) {
                    const unsigned* Kp = Kc + (nt * 8 + grp) * KV_STR + kb * 8;
                    mma_f16(sc[nt], qa[kb], Kp[tig], Kp[tig + 4]);
                }
            }

            // ---- online softmax (exp2) ----
            float mt0 = -1e30f, mt1 = -1e30f;
#pragma unroll
            for (int nt = 0; nt < 8; nt++) {
                mt0 = fmaxf(mt0, fmaxf(sc[nt][0], sc[nt][1]));
                mt1 = fmaxf(mt1, fmaxf(sc[nt][2], sc[nt][3]));
            }
            mt0 = fmaxf(mt0, __shfl_xor_sync(0xffffffff, mt0, 1));
            mt0 = fmaxf(mt0, __shfl_xor_sync(0xffffffff, mt0, 2));
            mt1 = fmaxf(mt1, __shfl_xor_sync(0xffffffff, mt1, 1));
            mt1 = fmaxf(mt1, __shfl_xor_sync(0xffffffff, mt1, 2));

            float mn0 = fmaxf(m0, mt0), mn1 = fmaxf(m1, mt1);
            float c0 = exp2f(m0 - mn0), c1 = exp2f(m1 - mn1);
            l0 *= c0; l1 *= c1;
            m0 = mn0; m1 = mn1;

#pragma unroll
            for (int nt = 0; nt < 8; nt++) {
                float p00 = exp2f(sc[nt][0] - mn0);
                float p01 = exp2f(sc[nt][1] - mn0);
                float p10 = exp2f(sc[nt][2] - mn1);
                float p11 = exp2f(sc[nt][3] - mn1);
                l0 += p00 + p01;
                l1 += p10 + p11;
                Pw[grp * PW_STR + nt * 4 + tig]       = f22h2(p00, p01);
                Pw[(grp + 8) * PW_STR + nt * 4 + tig] = f22h2(p10, p11);
                acc[nt][0] *= c0; acc[nt][1] *= c0;
                acc[nt][2] *= c1; acc[nt][3] *= c1;
            }
            __syncwarp();

            // ---- acc += P @ V (V stored d-major) ----
#pragma unroll
            for (int kb = 0; kb < 4; kb++) {
                unsigned a[4];
                a[0] = Pw[grp * PW_STR + kb * 8 + tig];
                a[1] = Pw[(grp + 8) * PW_STR + kb * 8 + tig];
                a[2] = Pw[grp * PW_STR + kb * 8 + tig + 4];
                a[3] = Pw[(grp + 8) * PW_STR + kb * 8 + tig + 4];
#pragma unroll
                for (int nt = 0; nt < 8; nt++) {
                    const unsigned* Vp = Vc + (nt * 8 + grp) * KV_STR + kb * 8;
                    mma_f16(acc[nt], a, Vp[tig], Vp[tig + 4]);
                }
            }
        }

        __syncthreads();
        if (tid == 0 && 2 * g + 4 < AT_NT) {
#pragma unroll
            for (int sub = 0; sub < 2; sub++) {
                const int t = 2 * g + 4 + sub;
                const int s = t & 3;
                mbar_expect(mb0 + 8 * s, 2 * KTILE_W * 4);
                bulk_g2s(smaddr(Ks + s * KTILE_W), ksrc + (size_t)t * KTILE_W, KTILE_W * 4, mb0 + 8 * s);
                bulk_g2s(smaddr(Vs + s * KTILE_W), vsrc + (size_t)t * KTILE_W, KTILE_W * 4, mb0 + 8 * s);
            }
        }
    }

    // ---- finalize: write fp16 XOR-swizzled A-tile layout for gemm_h<2> ----
    l0 += __shfl_xor_sync(0xffffffff, l0, 1);
    l0 += __shfl_xor_sync(0xffffffff, l0, 2);
    l1 += __shfl_xor_sync(0xffffffff, l1, 1);
    l1 += __shfl_xor_sync(0xffffffff, l1, 2);
    float inv0 = 1.f / l0, inv1 = 1.f / l1;

    int r0 = qb * 256 + w * 16 + grp;
    int r1 = r0 + 8;
#pragma unroll
    for (int nt = 0; nt < 8; nt++) {
        int col = h * HDIM + nt * 8 + 2 * tig;
        int kt = col >> 4;
        int wd = (col & 15) >> 1;
        {
            unsigned* base = g_attn_h + ((size_t)((r0 >> 7) * 64 + kt)) * GT_W + (r0 & 127) * 8;
            base[wd ^ (r0 & 7)] = f22h2(acc[nt][0] * inv0, acc[nt][1] * inv0);
        }
        {
            unsigned* base = g_attn_h + ((size_t)((r1 >> 7) * 64 + kt)) * GT_W + (r1 & 127) * 8;
            base[wd ^ (r1 & 7)] = f22h2(acc[nt][2] * inv1, acc[nt][3] * inv1);
        }
    }
}

// ---------------------------------------------------------------------------
extern "C" void kernel_launch(void* const* d_in, const int* in_sizes, int n_in,
                              void* d_out, int out_size)
{
    const float* utter = (const float*)d_in[0];
    const float* rctx  = (const float*)d_in[1];
    const float* mem   = (const float*)d_in[2];
    const float* lck   = (const float*)d_in[3];
    const float* lcv   = (const float*)d_in[4];
    const float* Wq    = (const float*)d_in[5];
    const float* bq    = (const float*)d_in[6];
    const float* Wkv   = (const float*)d_in[7];
    const float* bkv   = (const float*)d_in[8];
    const float* Wo    = (const float*)d_in[9];
    const float* bo    = (const float*)d_in[10];

    float* out = (float*)d_out;                       // [2304, 1024]
    float* key = out + (size_t)QLEN * D_DIM;          // [3840, 1024]
    float* val = key + (size_t)KVLEN * D_DIM;         // [3840, 1024]

    static bool attr_done = false;
    if (!attr_done) {
        cudaFuncSetAttribute(attn_mma, cudaFuncAttributeMaxDynamicSharedMemorySize, ATT_SMEM);
        cudaFuncSetAttribute(gemm_h<0>, cudaFuncAttributeMaxDynamicSharedMemorySize, GEMM_SMEM);
        cudaFuncSetAttribute(gemm_h<1>, cudaFuncAttributeMaxDynamicSharedMemorySize, GEMM_SMEM);
        cudaFuncSetAttribute(gemm_h<2>, cudaFuncAttributeMaxDynamicSharedMemorySize, GEMM_SMEM);
        attr_done = true;
    }

    unsigned *wq_p, *wkv_p, *wo_p;
    cudaGetSymbolAddress((void**)&wq_p,  g_Wq_h);
    cudaGetSymbolAddress((void**)&wkv_p, g_Wkv_h);
    cudaGetSymbolAddress((void**)&wo_p,  g_Wo_h);

    // 0) prepass conversions (fp16)
    conv_w_h<<<256, 256>>>(Wq,  wq_p,  D_DIM * D_DIM / 4);
    conv_w_h<<<512, 256>>>(Wkv, wkv_p, 2 * D_DIM * D_DIM / 4);
    conv_w_h<<<256, 256>>>(Wo,  wo_p,  D_DIM * D_DIM / 4);
    conv_kvin_h<<<512, 256>>>(utter, rctx, mem);
    conv_lc<<<256, 256>>>(lck, lcv);

    // 1) query projection -> g_query_h (fp16, pre-scaled, log2 domain)
    gemm_h<0><<<dim3(D_DIM / 128, QLEN / 128), 256, GEMM_SMEM>>>(bq, nullptr, nullptr);

    // 2) kv projection -> key/value (fp32) + fp16 K / V^T
    gemm_h<1><<<dim3(2 * D_DIM / 128, KVIN / 128), 256, GEMM_SMEM>>>(bkv, key, val);

    // 3) left-context splice into d_out (contiguous)
    cudaMemcpyAsync(key + (size_t)MR * D_DIM, lck,
                    (size_t)L_LEN * D_DIM * sizeof(float),
                    cudaMemcpyDeviceToDevice, 0);
    cudaMemcpyAsync(val + (size_t)MR * D_DIM, lcv,
                    (size_t)L_LEN * D_DIM * sizeof(float),
                    cudaMemcpyDeviceToDevice, 0);

    // 4) attention -> g_attn_h (fp16 tiles)
    attn_mma<<<dim3(NHEAD, QLEN / 256), 512, ATT_SMEM>>>(0);

    // 5) output projection
    gemm_h<2><<<dim3(D_DIM / 128, QLEN / 128), 256, GEMM_SMEM>>>(bo, out, nullptr);
}

// round 14
// speedup vs baseline: 1.6893x; 1.0989x over previous
#include <cuda_runtime.h>
#include <cuda_fp16.h>

// Problem dims
#define U_LEN 2048
#define R_LEN 256
#define L_LEN 1024
#define M_LEN 512
#define D_DIM 1024
#define NHEAD 16
#define HDIM  64
#define QLEN  (U_LEN + R_LEN)                   // 2304
#define KVLEN (M_LEN + R_LEN + L_LEN + U_LEN)   // 3840
#define MR    (M_LEN + R_LEN)                   // 768
#define KVIN  (MR + U_LEN)                      // 2816

// GEMM tiles: 128 rows x 16 halves = 1024 words (4KB), XOR swizzle w^(r&7)
#define GT_W 1024
#define GT_B 4096
#define NKT  64

// Attention K / V^T: rows of 64 halves = 32 words + 4 pad = stride 36 words
#define KV_STR   36
#define KTILE_W  (64 * KV_STR)       // 2304 words = 9216 B
#define KHEAD_W  (KVLEN * KV_STR)    // 138240 words
#define NVTILES  (KVLEN / 64)        // 60

// log2(e) folded into q scaling
#define QSCALE (0.125f * 1.4426950408889634f)

// Scratch (no cudaMalloc allowed)
__device__ __align__(16) unsigned g_kvin_h [22 * 64 * GT_W];
__device__ __align__(16) unsigned g_attn_h [18 * 64 * GT_W];
__device__ __align__(16) unsigned g_Wq_h   [ 8 * 64 * GT_W];
__device__ __align__(16) unsigned g_Wkv_h  [16 * 64 * GT_W];
__device__ __align__(16) unsigned g_Wo_h   [ 8 * 64 * GT_W];
__device__ __align__(16) unsigned g_query_h[QLEN * 512];          // fp16 row-major
__device__ __align__(16) unsigned g_key_h  [NHEAD * KHEAD_W];     // [head][row][36w]
__device__ __align__(16) __half   g_val_h  [NHEAD * NVTILES * 64 * 72]; // [head][tile][d][72h]

// ---------------------------------------------------------------------------
// helpers
// ---------------------------------------------------------------------------
__device__ __forceinline__ unsigned f22h2(float a, float b) {
    __half2 h = __floats2half2_rn(a, b);
    return *reinterpret_cast<unsigned*>(&h);
}

__device__ __forceinline__ void mma_f16(float* d, const unsigned* a, unsigned b0, unsigned b1) {
    asm volatile(
        "mma.sync.aligned.m16n8k16.row.col.f32.f16.f16.f32 "
        "{%0,%1,%2,%3}, {%4,%5,%6,%7}, {%8,%9}, {%0,%1,%2,%3};"
        : "+f"(d[0]), "+f"(d[1]), "+f"(d[2]), "+f"(d[3])
        : "r"(a[0]), "r"(a[1]), "r"(a[2]), "r"(a[3]), "r"(b0), "r"(b1));
}

__device__ __forceinline__ unsigned smaddr(const void* p) {
    return (unsigned)__cvta_generic_to_shared(p);
}
__device__ __forceinline__ void mbar_init(unsigned a) {
    asm volatile("mbarrier.init.shared.b64 [%0], 1;" :: "r"(a) : "memory");
}
__device__ __forceinline__ void mbar_expect(unsigned a, unsigned tx) {
    asm volatile("mbarrier.arrive.expect_tx.shared.b64 _, [%0], %1;" :: "r"(a), "r"(tx) : "memory");
}
__device__ __forceinline__ void bulk_g2s(unsigned sdst, const void* gsrc, unsigned bytes, unsigned mbar) {
    asm volatile("cp.async.bulk.shared::cta.global.mbarrier::complete_tx::bytes [%0], [%1], %2, [%3];"
                 :: "r"(sdst), "l"(gsrc), "r"(bytes), "r"(mbar) : "memory");
}
__device__ __forceinline__ void mbar_wait(unsigned a, unsigned ph) {
    asm volatile(
        "{\n\t.reg .pred P;\n\t"
        "WL%=:\n\t"
        "mbarrier.try_wait.parity.acquire.cta.shared::cta.b64 P, [%0], %1, 0x989680;\n\t"
        "@P bra WD%=;\n\t"
        "bra WL%=;\n\t"
        "WD%=:\n\t}"
        :: "r"(a), "r"(ph) : "memory");
}

// ---------------------------------------------------------------------------
// Prepass: weights -> fp16 XOR-swizzled GEMM tiles
// ---------------------------------------------------------------------------
__global__ void conv_w_h(const float* __restrict__ src, unsigned* __restrict__ dst, int n4)
{
    int i = blockIdx.x * blockDim.x + threadIdx.x;
    for (; i < n4; i += gridDim.x * blockDim.x) {
        int row = i >> 8;                // K=1024 -> 256 float4/row
        int col = (i & 255) * 4;
        float4 v = ((const float4*)src)[i];
        unsigned* base = dst + ((size_t)((row >> 7) * 64 + (col >> 4))) * GT_W + (row & 127) * 8;
        int rx = row & 7;
        int w0 = (col & 15) >> 1;        // 0,2,4,6
        base[w0 ^ rx]       = f22h2(v.x, v.y);
        base[(w0 + 1) ^ rx] = f22h2(v.z, v.w);
    }
}

// Prepass: gather concat(mem, rctx, utter) -> fp16 A tiles
__global__ void conv_kvin_h(const float* __restrict__ utter,
                            const float* __restrict__ rctx,
                            const float* __restrict__ mem)
{
    int i = blockIdx.x * blockDim.x + threadIdx.x;
    const int n4 = KVIN * D_DIM / 4;
    for (; i < n4; i += gridDim.x * blockDim.x) {
        int row = i >> 8;
        int col = (i & 255) * 4;
        const float4* s = (row < M_LEN)
            ? (const float4*)(mem + (size_t)row * D_DIM + col)
            : (row < MR)
            ? (const float4*)(rctx + (size_t)(row - M_LEN) * D_DIM + col)
            : (const float4*)(utter + (size_t)(row - MR) * D_DIM + col);
        float4 v = *s;
        unsigned* base = g_kvin_h + ((size_t)((row >> 7) * 64 + (col >> 4))) * GT_W + (row & 127) * 8;
        int rx = row & 7;
        int w0 = (col & 15) >> 1;
        base[w0 ^ rx]       = f22h2(v.x, v.y);
        base[(w0 + 1) ^ rx] = f22h2(v.z, v.w);
    }
}

// Prepass: left-context rows into fp16 K (row-major) and V^T (d-major)
__global__ void conv_lc(const float* __restrict__ lck, const float* __restrict__ lcv)
{
    int i = blockIdx.x * blockDim.x + threadIdx.x;
    const int n4 = L_LEN * D_DIM / 4;
    for (; i < n4; i += gridDim.x * blockDim.x) {
        int row = i >> 8;
        int col = (i & 255) * 4;
        int head = col >> 6, c = col & 63;
        int krow = MR + row;
        float4 k4 = *(const float4*)(lck + (size_t)row * D_DIM + col);
        float4 v4 = *(const float4*)(lcv + (size_t)row * D_DIM + col);
        // K: [head][krow][36w]
        unsigned* kb = g_key_h + ((size_t)head * KVLEN + krow) * KV_STR;
        kb[(c >> 1)]     = f22h2(k4.x, k4.y);
        kb[(c >> 1) + 1] = f22h2(k4.z, k4.w);
        // V^T: [head][tile][d][72h], element j = krow%64
        int tile = krow >> 6, j = krow & 63;
        __half* vb = g_val_h + (((size_t)head * NVTILES + tile) * 64 + c) * 72 + j;
        vb[0]      = __float2half_rn(v4.x);
        vb[72]     = __float2half_rn(v4.y);
        vb[144]    = __float2half_rn(v4.z);
        vb[216]    = __float2half_rn(v4.w);
    }
}

// ---------------------------------------------------------------------------
// FP16 GEMM, bulk-copy 4-stage pipeline: C = A @ W^T + bias
// BM=BN=128, BK=16, 256 threads (8 warps 4x2); m16n8k16 -> 16 MMA/ktile/warp.
// MODE 0: A=kvin blocks 4..21 (q_in) -> g_query_h (fp16, pre-scaled, log2)
// MODE 1: A=kvin blocks 0..21        -> key/value fp32 + fp16 K / V^T
// MODE 2: A=g_attn_h                 -> out fp32
// ---------------------------------------------------------------------------
#define GEMM_SMEM (8 * GT_W * 4 + 64)

template <int MODE>
__global__ __launch_bounds__(256, 2)
void gemm_h(const float* __restrict__ bias,
            float* __restrict__ C0,
            float* __restrict__ C1)
{
    extern __shared__ unsigned gsm[];
    unsigned* As = gsm;               // [4][1024]
    unsigned* Bs = gsm + 4 * GT_W;    // [4][1024]
    const unsigned mb0 = smaddr(gsm + 8 * GT_W);

    const int tid  = threadIdx.x;
    const int lane = tid & 31;
    const int warp = tid >> 5;
    const int wr   = warp & 3;
    const int wc   = warp >> 2;
    const int bm = blockIdx.y, bn = blockIdx.x;
    const int tig = lane & 3, grp = lane >> 2;

    const unsigned* Ab =
        (MODE == 0) ? g_kvin_h + (size_t)(bm + 4) * 64 * GT_W
      : (MODE == 1) ? g_kvin_h + (size_t)bm * 64 * GT_W
                    : g_attn_h + (size_t)bm * 64 * GT_W;
    const unsigned* Wb =
        ((MODE == 0) ? g_Wq_h : (MODE == 1) ? g_Wkv_h : g_Wo_h)
        + (size_t)bn * 64 * GT_W;

    if (tid == 0) {
        mbar_init(mb0); mbar_init(mb0 + 8); mbar_init(mb0 + 16); mbar_init(mb0 + 24);
    }
    __syncthreads();
    if (tid == 0) {
#pragma unroll
        for (int s = 0; s < 4; s++) {
            mbar_expect(mb0 + 8 * s, 2 * GT_B);
            bulk_g2s(smaddr(As + s * GT_W), Ab + (size_t)s * GT_W, GT_B, mb0 + 8 * s);
            bulk_g2s(smaddr(Bs + s * GT_W), Wb + (size_t)s * GT_W, GT_B, mb0 + 8 * s);
        }
    }

    float acc[2][8][4];
#pragma unroll
    for (int mt = 0; mt < 2; mt++)
#pragma unroll
        for (int nt = 0; nt < 8; nt++)
#pragma unroll
            for (int i = 0; i < 4; i++) acc[mt][nt][i] = 0.f;

    const int x0 = tig ^ grp;
    const int x1 = (tig + 4) ^ grp;

    for (int g = 0; g < NKT / 2; g++) {
#pragma unroll
        for (int sub = 0; sub < 2; sub++) {
            const int kt = 2 * g + sub;
            const int s  = kt & 3;
            mbar_wait(mb0 + 8 * s, (unsigned)((kt >> 2) & 1));

            const unsigned* Asl = As + s * GT_W;
            const unsigned* Bsl = Bs + s * GT_W;

            unsigned b[8][2];
#pragma unroll
            for (int nt = 0; nt < 8; nt++) {
                const unsigned* Bp = Bsl + (wc * 64 + nt * 8 + grp) * 8;
                b[nt][0] = Bp[x0];
                b[nt][1] = Bp[x1];
            }
#pragma unroll
            for (int mt = 0; mt < 2; mt++) {
                const unsigned* A0 = Asl + (wr * 32 + mt * 16 + grp) * 8;
                const unsigned* A1 = A0 + 64;
                unsigned a[4];
                a[0] = A0[x0]; a[1] = A1[x0]; a[2] = A0[x1]; a[3] = A1[x1];
#pragma unroll
                for (int nt = 0; nt < 8; nt++) mma_f16(acc[mt][nt], a, b[nt][0], b[nt][1]);
            }
        }
        __syncthreads();
        if (tid == 0 && 2 * g + 4 < NKT) {
#pragma unroll
            for (int sub = 0; sub < 2; sub++) {
                const int kt = 2 * g + 4 + sub;
                const int s  = kt & 3;
                mbar_expect(mb0 + 8 * s, 2 * GT_B);
                bulk_g2s(smaddr(As + s * GT_W), Ab + (size_t)kt * GT_W, GT_B, mb0 + 8 * s);
                bulk_g2s(smaddr(Bs + s * GT_W), Wb + (size_t)kt * GT_W, GT_B, mb0 + 8 * s);
            }
        }
    }

    // epilogue
#pragma unroll
    for (int mt = 0; mt < 2; mt++) {
#pragma unroll
        for (int nt = 0; nt < 8; nt++) {
            int col = bn * 128 + wc * 64 + nt * 8 + 2 * tig;
#pragma unroll
            for (int half = 0; half < 2; half++) {
                int row = bm * 128 + wr * 32 + mt * 16 + grp + half * 8;
                float v0 = acc[mt][nt][half * 2 + 0] + bias[col];
                float v1 = acc[mt][nt][half * 2 + 1] + bias[col + 1];
                if (MODE == 0) {
                    g_query_h[(size_t)row * 512 + (col >> 1)] =
                        f22h2(v0 * QSCALE, v1 * QSCALE);
                } else if (MODE == 1) {
                    int krow = (row < MR) ? row : row + L_LEN;
                    if (col < D_DIM) {
                        *(float2*)(C0 + (size_t)krow * D_DIM + col) = make_float2(v0, v1);
                        int head = col >> 6, c = col & 63;
                        g_key_h[((size_t)head * KVLEN + krow) * KV_STR + (c >> 1)] = f22h2(v0, v1);
                    } else {
                        int vc = col - D_DIM;
                        *(float2*)(C1 + (size_t)krow * D_DIM + vc) = make_float2(v0, v1);
                        int head = vc >> 6, c = vc & 63;
                        int tile = krow >> 6, j = krow & 63;
                        __half* vb = g_val_h + (((size_t)head * NVTILES + tile) * 64 + c) * 72 + j;
                        vb[0]  = __float2half_rn(v0);
                        vb[72] = __float2half_rn(v1);
                    }
                } else {
                    *(float2*)(C0 + (size_t)row * D_DIM + col) = make_float2(v0, v1);
                }
            }
        }
    }
}

// ---------------------------------------------------------------------------
// FP16 tensor-core flash attention, 512 threads = 256 q rows of one head.
// 4-stage bulk pipeline, sync per 2 tiles. m16n8k16; softmax in log2 domain.
// ---------------------------------------------------------------------------
#define AT_NT   NVTILES    // 60
#define PW_STR  36
#define ATT_SMEM ((8 * KTILE_W + 16 * 16 * PW_STR) * 4 + 64)

__global__ __launch_bounds__(512, 1)
void attn_mma(int dummy)
{
    extern __shared__ unsigned sm[];
    unsigned* Ks = sm;                           // [4][2304]
    unsigned* Vs = sm + 4 * KTILE_W;             // [4][2304]
    unsigned* Pa = sm + 8 * KTILE_W;             // [16][16*36]
    const unsigned mb0 = smaddr(Pa + 16 * 16 * PW_STR);

    const int h   = blockIdx.x;
    const int qb  = blockIdx.y;
    const int tid = threadIdx.x;
    const int lane = tid & 31;
    const int w    = tid >> 5;
    const int grp  = lane >> 2;
    const int tig  = lane & 3;
    unsigned* Pw = Pa + w * 16 * PW_STR;

    const unsigned* ksrc = g_key_h + (size_t)h * KHEAD_W;
    const unsigned* vsrc = (const unsigned*)(g_val_h + (size_t)h * NVTILES * 64 * 72);

    if (tid == 0) {
        mbar_init(mb0); mbar_init(mb0 + 8); mbar_init(mb0 + 16); mbar_init(mb0 + 24);
    }
    __syncthreads();
    if (tid == 0) {
#pragma unroll
        for (int s = 0; s < 4; s++) {
            mbar_expect(mb0 + 8 * s, 2 * KTILE_W * 4);
            bulk_g2s(smaddr(Ks + s * KTILE_W), ksrc + (size_t)s * KTILE_W, KTILE_W * 4, mb0 + 8 * s);
            bulk_g2s(smaddr(Vs + s * KTILE_W), vsrc + (size_t)s * KTILE_W, KTILE_W * 4, mb0 + 8 * s);
        }
    }

    // Q fragments (fp16, pre-scaled, log2 domain)
    unsigned qa[4][4];
    {
        const unsigned* q0 = g_query_h + (size_t)(qb * 256 + w * 16 + grp) * 512 + h * 32;
        const unsigned* q1 = q0 + 8 * 512;
#pragma unroll
        for (int kb = 0; kb < 4; kb++) {
            qa[kb][0] = q0[kb * 8 + tig];
            qa[kb][1] = q1[kb * 8 + tig];
            qa[kb][2] = q0[kb * 8 + tig + 4];
            qa[kb][3] = q1[kb * 8 + tig + 4];
        }
    }

    float acc[8][4];
#pragma unroll
    for (int nt = 0; nt < 8; nt++)
#pragma unroll
        for (int i = 0; i < 4; i++) acc[nt][i] = 0.f;
    float m0 = -1e30f, m1 = -1e30f, l0 = 0.f, l1 = 0.f;

    for (int g = 0; g < AT_NT / 2; g++) {
#pragma unroll
        for (int sub = 0; sub < 2; sub++) {
            const int t = 2 * g + sub;
            const int s = t & 3;
            mbar_wait(mb0 + 8 * s, (unsigned)((t >> 2) & 1));

            const unsigned* Kc = Ks + s * KTILE_W;
            const unsigned* Vc = Vs + s * KTILE_W;

            // ---- S = Q K^T (log2 domain) ----
            float sc[8][4];
#pragma unroll
            for (int nt = 0; nt < 8; nt++)
#pragma unroll
                for (int i = 0; i < 4; i++) sc[nt][i] = 0.f;
#pragma unroll
            for (int kb = 0; kb < 4; kb++) {
#pragma unroll
                for (int nt = 0; nt < 8; nt++) {
                    const unsigned* Kp = Kc + (nt * 8 + grp) * KV_STR + kb * 8;
                    mma_f16(sc[nt], qa[kb], Kp[tig], Kp[tig + 4]);
                }
            }

            // ---- online softmax (exp2) ----
            float mt0 = -1e30f, mt1 = -1e30f;
#pragma unroll
            for (int nt = 0; nt < 8; nt++) {
                mt0 = fmaxf(mt0, fmaxf(sc[nt][0], sc[nt][1]));
                mt1 = fmaxf(mt1, fmaxf(sc[nt][2], sc[nt][3]));
            }
            mt0 = fmaxf(mt0, __shfl_xor_sync(0xffffffff, mt0, 1));
            mt0 = fmaxf(mt0, __shfl_xor_sync(0xffffffff, mt0, 2));
            mt1 = fmaxf(mt1, __shfl_xor_sync(0xffffffff, mt1, 1));
            mt1 = fmaxf(mt1, __shfl_xor_sync(0xffffffff, mt1, 2));

            float mn0 = fmaxf(m0, mt0), mn1 = fmaxf(m1, mt1);
            float c0 = exp2f(m0 - mn0), c1 = exp2f(m1 - mn1);
            l0 *= c0; l1 *= c1;
            m0 = mn0; m1 = mn1;

#pragma unroll
            for (int nt = 0; nt < 8; nt++) {
                float p00 = exp2f(sc[nt][0] - mn0);
                float p01 = exp2f(sc[nt][1] - mn0);
                float p10 = exp2f(sc[nt][2] - mn1);
                float p11 = exp2f(sc[nt][3] - mn1);
                l0 += p00 + p01;
                l1 += p10 + p11;
                Pw[grp * PW_STR + nt * 4 + tig]       = f22h2(p00, p01);
                Pw[(grp + 8) * PW_STR + nt * 4 + tig] = f22h2(p10, p11);
                acc[nt][0] *= c0; acc[nt][1] *= c0;
                acc[nt][2] *= c1; acc[nt][3] *= c1;
            }
            __syncwarp();

            // ---- acc += P @ V (V stored d-major) ----
#pragma unroll
            for (int kb = 0; kb < 4; kb++) {
                unsigned a[4];
                a[0] = Pw[grp * PW_STR + kb * 8 + tig];
                a[1] = Pw[(grp + 8) * PW_STR + kb * 8 + tig];
                a[2] = Pw[grp * PW_STR + kb * 8 + tig + 4];
                a[3] = Pw[(grp + 8) * PW_STR + kb * 8 + tig + 4];
#pragma unroll
                for (int nt = 0; nt < 8; nt++) {
                    const unsigned* Vp = Vc + (nt * 8 + grp) * KV_STR + kb * 8;
                    mma_f16(acc[nt], a, Vp[tig], Vp[tig + 4]);
                }
            }
        }

        __syncthreads();
        if (tid == 0 && 2 * g + 4 < AT_NT) {
#pragma unroll
            for (int sub = 0; sub < 2; sub++) {
                const int t = 2 * g + 4 + sub;
                const int s = t & 3;
                mbar_expect(mb0 + 8 * s, 2 * KTILE_W * 4);
                bulk_g2s(smaddr(Ks + s * KTILE_W), ksrc + (size_t)t * KTILE_W, KTILE_W * 4, mb0 + 8 * s);
                bulk_g2s(smaddr(Vs + s * KTILE_W), vsrc + (size_t)t * KTILE_W, KTILE_W * 4, mb0 + 8 * s);
            }
        }
    }

    // ---- finalize: write fp16 XOR-swizzled A-tile layout for gemm_h<2> ----
    l0 += __shfl_xor_sync(0xffffffff, l0, 1);
    l0 += __shfl_xor_sync(0xffffffff, l0, 2);
    l1 += __shfl_xor_sync(0xffffffff, l1, 1);
    l1 += __shfl_xor_sync(0xffffffff, l1, 2);
    float inv0 = 1.f / l0, inv1 = 1.f / l1;

    int r0 = qb * 256 + w * 16 + grp;
    int r1 = r0 + 8;
#pragma unroll
    for (int nt = 0; nt < 8; nt++) {
        int col = h * HDIM + nt * 8 + 2 * tig;
        int kt = col >> 4;
        int wd = (col & 15) >> 1;
        {
            unsigned* base = g_attn_h + ((size_t)((r0 >> 7) * 64 + kt)) * GT_W + (r0 & 127) * 8;
            base[wd ^ (r0 & 7)] = f22h2(acc[nt][0] * inv0, acc[nt][1] * inv0);
        }
        {
            unsigned* base = g_attn_h + ((size_t)((r1 >> 7) * 64 + kt)) * GT_W + (r1 & 127) * 8;
            base[wd ^ (r1 & 7)] = f22h2(acc[nt][2] * inv1, acc[nt][3] * inv1);
        }
    }
}

// ---------------------------------------------------------------------------
extern "C" void kernel_launch(void* const* d_in, const int* in_sizes, int n_in,
                              void* d_out, int out_size)
{
    const float* utter = (const float*)d_in[0];
    const float* rctx  = (const float*)d_in[1];
    const float* mem   = (const float*)d_in[2];
    const float* lck   = (const float*)d_in[3];
    const float* lcv   = (const float*)d_in[4];
    const float* Wq    = (const float*)d_in[5];
    const float* bq    = (const float*)d_in[6];
    const float* Wkv   = (const float*)d_in[7];
    const float* bkv   = (const float*)d_in[8];
    const float* Wo    = (const float*)d_in[9];
    const float* bo    = (const float*)d_in[10];

    float* out = (float*)d_out;                       // [2304, 1024]
    float* key = out + (size_t)QLEN * D_DIM;          // [3840, 1024]
    float* val = key + (size_t)KVLEN * D_DIM;         // [3840, 1024]

    static cudaStream_t s1 = nullptr;
    static cudaEvent_t eFork = nullptr, eP1 = nullptr, eG1 = nullptr, eTail = nullptr;
    if (!s1) {
        cudaFuncSetAttribute(attn_mma, cudaFuncAttributeMaxDynamicSharedMemorySize, ATT_SMEM);
        cudaFuncSetAttribute(gemm_h<0>, cudaFuncAttributeMaxDynamicSharedMemorySize, GEMM_SMEM);
        cudaFuncSetAttribute(gemm_h<1>, cudaFuncAttributeMaxDynamicSharedMemorySize, GEMM_SMEM);
        cudaFuncSetAttribute(gemm_h<2>, cudaFuncAttributeMaxDynamicSharedMemorySize, GEMM_SMEM);
        cudaStreamCreateWithFlags(&s1, cudaStreamNonBlocking);
        cudaEventCreateWithFlags(&eFork, cudaEventDisableTiming);
        cudaEventCreateWithFlags(&eP1,   cudaEventDisableTiming);
        cudaEventCreateWithFlags(&eG1,   cudaEventDisableTiming);
        cudaEventCreateWithFlags(&eTail, cudaEventDisableTiming);
    }

    unsigned *wq_p, *wkv_p, *wo_p;
    cudaGetSymbolAddress((void**)&wq_p,  g_Wq_h);
    cudaGetSymbolAddress((void**)&wkv_p, g_Wkv_h);
    cudaGetSymbolAddress((void**)&wo_p,  g_Wo_h);

    // ---- fork s1 off the capture (legacy) stream ----
    cudaEventRecord(eFork, 0);
    cudaStreamWaitEvent(s1, eFork, 0);

    // ---- s0 chain: kvin -> Wq -> gemm0 (q proj) ----
    conv_kvin_h<<<512, 256, 0, 0>>>(utter, rctx, mem);
    cudaEventRecord(eP1, 0);                       // kvin ready
    conv_w_h<<<256, 256, 0, 0>>>(Wq, wq_p, D_DIM * D_DIM / 4);
    gemm_h<0><<<dim3(D_DIM / 128, QLEN / 128), 256, GEMM_SMEM, 0>>>(bq, nullptr, nullptr);

    // ---- s1 chain: Wkv -> lc -> (wait kvin) gemm1 -> Wo -> memcpys ----
    conv_w_h<<<512, 256, 0, s1>>>(Wkv, wkv_p, 2 * D_DIM * D_DIM / 4);
    conv_lc<<<256, 256, 0, s1>>>(lck, lcv);
    cudaStreamWaitEvent(s1, eP1, 0);
    gemm_h<1><<<dim3(2 * D_DIM / 128, KVIN / 128), 256, GEMM_SMEM, s1>>>(bkv, key, val);
    cudaEventRecord(eG1, s1);                      // kv + lc ready for attention
    conv_w_h<<<256, 256, 0, s1>>>(Wo, wo_p, D_DIM * D_DIM / 4);
    cudaMemcpyAsync(key + (size_t)MR * D_DIM, lck,
                    (size_t)L_LEN * D_DIM * sizeof(float),
                    cudaMemcpyDeviceToDevice, s1);
    cudaMemcpyAsync(val + (size_t)MR * D_DIM, lcv,
                    (size_t)L_LEN * D_DIM * sizeof(float),
                    cudaMemcpyDeviceToDevice, s1);
    cudaEventRecord(eTail, s1);                    // Wo + d_out splices done

    // ---- s0: attention (overlaps conv_wo + memcpys), then join + gemm2 ----
    cudaStreamWaitEvent(0, eG1, 0);
    attn_mma<<<dim3(NHEAD, QLEN / 256), 512, ATT_SMEM, 0>>>(0);
    cudaStreamWaitEvent(0, eTail, 0);              // join s1 back into capture stream
    gemm_h<2><<<dim3(D_DIM / 128, QLEN / 128), 256, GEMM_SMEM, 0>>>(bo, out, nullptr);
}

// round 15
// speedup vs baseline: 1.8503x; 1.0954x over previous
#include <cuda_runtime.h>
#include <cuda_fp16.h>

// Problem dims
#define U_LEN 2048
#define R_LEN 256
#define L_LEN 1024
#define M_LEN 512
#define D_DIM 1024
#define NHEAD 16
#define HDIM  64
#define QLEN  (U_LEN + R_LEN)                   // 2304
#define KVLEN (M_LEN + R_LEN + L_LEN + U_LEN)   // 3840
#define MR    (M_LEN + R_LEN)                   // 768
#define KVIN  (MR + U_LEN)                      // 2816

// GEMM tiles: 128 rows x 16 halves = 1024 words (4KB), XOR swizzle w^(r&7)
#define GT_W 1024
#define GT_B 4096
#define NKT  64

// Attention K / V^T: rows of 64 halves = 32 words + 4 pad = stride 36 words
#define KV_STR   36
#define KTILE_W  (64 * KV_STR)       // 2304 words = 9216 B
#define KHEAD_W  (KVLEN * KV_STR)    // 138240 words
#define NVTILES  (KVLEN / 64)        // 60

// log2(e) folded into q scaling
#define QSCALE (0.125f * 1.4426950408889634f)

// Scratch (no cudaMalloc allowed)
__device__ __align__(16) unsigned g_kvin_h [22 * 64 * GT_W];
__device__ __align__(16) unsigned g_attn_h [18 * 64 * GT_W];
__device__ __align__(16) unsigned g_Wq_h   [ 8 * 64 * GT_W];
__device__ __align__(16) unsigned g_Wkv_h  [16 * 64 * GT_W];
__device__ __align__(16) unsigned g_Wo_h   [ 8 * 64 * GT_W];
__device__ __align__(16) unsigned g_query_h[QLEN * 512];          // fp16 row-major
__device__ __align__(16) unsigned g_key_h  [NHEAD * KHEAD_W];     // [head][row][36w]
__device__ __align__(16) __half   g_val_h  [NHEAD * NVTILES * 64 * 72]; // [head][tile][d][72h]

// ---------------------------------------------------------------------------
// helpers
// ---------------------------------------------------------------------------
__device__ __forceinline__ unsigned f22h2(float a, float b) {
    __half2 h = __floats2half2_rn(a, b);
    return *reinterpret_cast<unsigned*>(&h);
}

// pack (lo=a, hi=b) and exp2 both halves in one MUFU op
__device__ __forceinline__ unsigned exp2_h2(float a, float b) {
    unsigned p, r;
    asm("cvt.rn.f16x2.f32 %0, %2, %1;" : "=r"(p) : "f"(a), "f"(b));
    asm("ex2.approx.f16x2 %0, %1;" : "=r"(r) : "r"(p));
    return r;
}

__device__ __forceinline__ unsigned hadd2u(unsigned a, unsigned b) {
    unsigned r;
    asm("add.f16x2 %0, %1, %2;" : "=r"(r) : "r"(a), "r"(b));
    return r;
}

__device__ __forceinline__ void mma_f16(float* d, const unsigned* a, unsigned b0, unsigned b1) {
    asm volatile(
        "mma.sync.aligned.m16n8k16.row.col.f32.f16.f16.f32 "
        "{%0,%1,%2,%3}, {%4,%5,%6,%7}, {%8,%9}, {%0,%1,%2,%3};"
        : "+f"(d[0]), "+f"(d[1]), "+f"(d[2]), "+f"(d[3])
        : "r"(a[0]), "r"(a[1]), "r"(a[2]), "r"(a[3]), "r"(b0), "r"(b1));
}

__device__ __forceinline__ unsigned smaddr(const void* p) {
    return (unsigned)__cvta_generic_to_shared(p);
}
__device__ __forceinline__ void mbar_init(unsigned a) {
    asm volatile("mbarrier.init.shared.b64 [%0], 1;" :: "r"(a) : "memory");
}
__device__ __forceinline__ void mbar_expect(unsigned a, unsigned tx) {
    asm volatile("mbarrier.arrive.expect_tx.shared.b64 _, [%0], %1;" :: "r"(a), "r"(tx) : "memory");
}
__device__ __forceinline__ void bulk_g2s(unsigned sdst, const void* gsrc, unsigned bytes, unsigned mbar) {
    asm volatile("cp.async.bulk.shared::cta.global.mbarrier::complete_tx::bytes [%0], [%1], %2, [%3];"
                 :: "r"(sdst), "l"(gsrc), "r"(bytes), "r"(mbar) : "memory");
}
__device__ __forceinline__ void mbar_wait(unsigned a, unsigned ph) {
    asm volatile(
        "{\n\t.reg .pred P;\n\t"
        "WL%=:\n\t"
        "mbarrier.try_wait.parity.acquire.cta.shared::cta.b64 P, [%0], %1, 0x989680;\n\t"
        "@P bra WD%=;\n\t"
        "bra WL%=;\n\t"
        "WD%=:\n\t}"
        :: "r"(a), "r"(ph) : "memory");
}

// ---------------------------------------------------------------------------
// Prepass: weights -> fp16 XOR-swizzled GEMM tiles
// ---------------------------------------------------------------------------
__global__ void conv_w_h(const float* __restrict__ src, unsigned* __restrict__ dst, int n4)
{
    int i = blockIdx.x * blockDim.x + threadIdx.x;
    for (; i < n4; i += gridDim.x * blockDim.x) {
        int row = i >> 8;                // K=1024 -> 256 float4/row
        int col = (i & 255) * 4;
        float4 v = ((const float4*)src)[i];
        unsigned* base = dst + ((size_t)((row >> 7) * 64 + (col >> 4))) * GT_W + (row & 127) * 8;
        int rx = row & 7;
        int w0 = (col & 15) >> 1;        // 0,2,4,6
        base[w0 ^ rx]       = f22h2(v.x, v.y);
        base[(w0 + 1) ^ rx] = f22h2(v.z, v.w);
    }
}

// Prepass: gather concat(mem, rctx, utter) -> fp16 A tiles
__global__ void conv_kvin_h(const float* __restrict__ utter,
                            const float* __restrict__ rctx,
                            const float* __restrict__ mem)
{
    int i = blockIdx.x * blockDim.x + threadIdx.x;
    const int n4 = KVIN * D_DIM / 4;
    for (; i < n4; i += gridDim.x * blockDim.x) {
        int row = i >> 8;
        int col = (i & 255) * 4;
        const float4* s = (row < M_LEN)
            ? (const float4*)(mem + (size_t)row * D_DIM + col)
            : (row < MR)
            ? (const float4*)(rctx + (size_t)(row - M_LEN) * D_DIM + col)
            : (const float4*)(utter + (size_t)(row - MR) * D_DIM + col);
        float4 v = *s;
        unsigned* base = g_kvin_h + ((size_t)((row >> 7) * 64 + (col >> 4))) * GT_W + (row & 127) * 8;
        int rx = row & 7;
        int w0 = (col & 15) >> 1;
        base[w0 ^ rx]       = f22h2(v.x, v.y);
        base[(w0 + 1) ^ rx] = f22h2(v.z, v.w);
    }
}

// Prepass: left-context rows into fp16 K (row-major) and V^T (d-major)
__global__ void conv_lc(const float* __restrict__ lck, const float* __restrict__ lcv)
{
    int i = blockIdx.x * blockDim.x + threadIdx.x;
    const int n4 = L_LEN * D_DIM / 4;
    for (; i < n4; i += gridDim.x * blockDim.x) {
        int row = i >> 8;
        int col = (i & 255) * 4;
        int head = col >> 6, c = col & 63;
        int krow = MR + row;
        float4 k4 = *(const float4*)(lck + (size_t)row * D_DIM + col);
        float4 v4 = *(const float4*)(lcv + (size_t)row * D_DIM + col);
        // K: [head][krow][36w]
        unsigned* kb = g_key_h + ((size_t)head * KVLEN + krow) * KV_STR;
        kb[(c >> 1)]     = f22h2(k4.x, k4.y);
        kb[(c >> 1) + 1] = f22h2(k4.z, k4.w);
        // V^T: [head][tile][d][72h], element j = krow%64
        int tile = krow >> 6, j = krow & 63;
        __half* vb = g_val_h + (((size_t)head * NVTILES + tile) * 64 + c) * 72 + j;
        vb[0]      = __float2half_rn(v4.x);
        vb[72]     = __float2half_rn(v4.y);
        vb[144]    = __float2half_rn(v4.z);
        vb[216]    = __float2half_rn(v4.w);
    }
}

// ---------------------------------------------------------------------------
// FP16 GEMM, bulk-copy 4-stage pipeline: C = A @ W^T + bias   (unchanged R12)
// ---------------------------------------------------------------------------
#define GEMM_SMEM (8 * GT_W * 4 + 64)

template <int MODE>
__global__ __launch_bounds__(256, 2)
void gemm_h(const float* __restrict__ bias,
            float* __restrict__ C0,
            float* __restrict__ C1)
{
    extern __shared__ unsigned gsm[];
    unsigned* As = gsm;               // [4][1024]
    unsigned* Bs = gsm + 4 * GT_W;    // [4][1024]
    const unsigned mb0 = smaddr(gsm + 8 * GT_W);

    const int tid  = threadIdx.x;
    const int lane = tid & 31;
    const int warp = tid >> 5;
    const int wr   = warp & 3;
    const int wc   = warp >> 2;
    const int bm = blockIdx.y, bn = blockIdx.x;
    const int tig = lane & 3, grp = lane >> 2;

    const unsigned* Ab =
        (MODE == 0) ? g_kvin_h + (size_t)(bm + 4) * 64 * GT_W
      : (MODE == 1) ? g_kvin_h + (size_t)bm * 64 * GT_W
                    : g_attn_h + (size_t)bm * 64 * GT_W;
    const unsigned* Wb =
        ((MODE == 0) ? g_Wq_h : (MODE == 1) ? g_Wkv_h : g_Wo_h)
        + (size_t)bn * 64 * GT_W;

    if (tid == 0) {
        mbar_init(mb0); mbar_init(mb0 + 8); mbar_init(mb0 + 16); mbar_init(mb0 + 24);
    }
    __syncthreads();
    if (tid == 0) {
#pragma unroll
        for (int s = 0; s < 4; s++) {
            mbar_expect(mb0 + 8 * s, 2 * GT_B);
            bulk_g2s(smaddr(As + s * GT_W), Ab + (size_t)s * GT_W, GT_B, mb0 + 8 * s);
            bulk_g2s(smaddr(Bs + s * GT_W), Wb + (size_t)s * GT_W, GT_B, mb0 + 8 * s);
        }
    }

    float acc[2][8][4];
#pragma unroll
    for (int mt = 0; mt < 2; mt++)
#pragma unroll
        for (int nt = 0; nt < 8; nt++)
#pragma unroll
            for (int i = 0; i < 4; i++) acc[mt][nt][i] = 0.f;

    const int x0 = tig ^ grp;
    const int x1 = (tig + 4) ^ grp;

    for (int g = 0; g < NKT / 2; g++) {
#pragma unroll
        for (int sub = 0; sub < 2; sub++) {
            const int kt = 2 * g + sub;
            const int s  = kt & 3;
            mbar_wait(mb0 + 8 * s, (unsigned)((kt >> 2) & 1));

            const unsigned* Asl = As + s * GT_W;
            const unsigned* Bsl = Bs + s * GT_W;

            unsigned b[8][2];
#pragma unroll
            for (int nt = 0; nt < 8; nt++) {
                const unsigned* Bp = Bsl + (wc * 64 + nt * 8 + grp) * 8;
                b[nt][0] = Bp[x0];
                b[nt][1] = Bp[x1];
            }
#pragma unroll
            for (int mt = 0; mt < 2; mt++) {
                const unsigned* A0 = Asl + (wr * 32 + mt * 16 + grp) * 8;
                const unsigned* A1 = A0 + 64;
                unsigned a[4];
                a[0] = A0[x0]; a[1] = A1[x0]; a[2] = A0[x1]; a[3] = A1[x1];
#pragma unroll
                for (int nt = 0; nt < 8; nt++) mma_f16(acc[mt][nt], a, b[nt][0], b[nt][1]);
            }
        }
        __syncthreads();
        if (tid == 0 && 2 * g + 4 < NKT) {
#pragma unroll
            for (int sub = 0; sub < 2; sub++) {
                const int kt = 2 * g + 4 + sub;
                const int s  = kt & 3;
                mbar_expect(mb0 + 8 * s, 2 * GT_B);
                bulk_g2s(smaddr(As + s * GT_W), Ab + (size_t)kt * GT_W, GT_B, mb0 + 8 * s);
                bulk_g2s(smaddr(Bs + s * GT_W), Wb + (size_t)kt * GT_W, GT_B, mb0 + 8 * s);
            }
        }
    }

    // epilogue
#pragma unroll
    for (int mt = 0; mt < 2; mt++) {
#pragma unroll
        for (int nt = 0; nt < 8; nt++) {
            int col = bn * 128 + wc * 64 + nt * 8 + 2 * tig;
#pragma unroll
            for (int half = 0; half < 2; half++) {
                int row = bm * 128 + wr * 32 + mt * 16 + grp + half * 8;
                float v0 = acc[mt][nt][half * 2 + 0] + bias[col];
                float v1 = acc[mt][nt][half * 2 + 1] + bias[col + 1];
                if (MODE == 0) {
                    g_query_h[(size_t)row * 512 + (col >> 1)] =
                        f22h2(v0 * QSCALE, v1 * QSCALE);
                } else if (MODE == 1) {
                    int krow = (row < MR) ? row : row + L_LEN;
                    if (col < D_DIM) {
                        *(float2*)(C0 + (size_t)krow * D_DIM + col) = make_float2(v0, v1);
                        int head = col >> 6, c = col & 63;
                        g_key_h[((size_t)head * KVLEN + krow) * KV_STR + (c >> 1)] = f22h2(v0, v1);
                    } else {
                        int vc = col - D_DIM;
                        *(float2*)(C1 + (size_t)krow * D_DIM + vc) = make_float2(v0, v1);
                        int head = vc >> 6, c = vc & 63;
                        int tile = krow >> 6, j = krow & 63;
                        __half* vb = g_val_h + (((size_t)head * NVTILES + tile) * 64 + c) * 72 + j;
                        vb[0]  = __float2half_rn(v0);
                        vb[72] = __float2half_rn(v1);
                    }
                } else {
                    *(float2*)(C0 + (size_t)row * D_DIM + col) = make_float2(v0, v1);
                }
            }
        }
    }
}

// ---------------------------------------------------------------------------
// FP16 flash attention with register-resident P and f16x2 exp2.
// 512 threads = 256 q rows of one head; 4-stage bulk pipeline.
// ---------------------------------------------------------------------------
#define AT_NT   NVTILES    // 60
#define ATT_SMEM (8 * KTILE_W * 4 + 64)

__global__ __launch_bounds__(512, 1)
void attn_mma(int dummy)
{
    extern __shared__ unsigned sm[];
    unsigned* Ks = sm;                           // [4][2304]
    unsigned* Vs = sm + 4 * KTILE_W;             // [4][2304]
    const unsigned mb0 = smaddr(sm + 8 * KTILE_W);

    const int h   = blockIdx.x;
    const int qb  = blockIdx.y;
    const int tid = threadIdx.x;
    const int lane = tid & 31;
    const int w    = tid >> 5;
    const int grp  = lane >> 2;
    const int tig  = lane & 3;

    const unsigned* ksrc = g_key_h + (size_t)h * KHEAD_W;
    const unsigned* vsrc = (const unsigned*)(g_val_h + (size_t)h * NVTILES * 64 * 72);

    if (tid == 0) {
        mbar_init(mb0); mbar_init(mb0 + 8); mbar_init(mb0 + 16); mbar_init(mb0 + 24);
    }
    __syncthreads();
    if (tid == 0) {
#pragma unroll
        for (int s = 0; s < 4; s++) {
            mbar_expect(mb0 + 8 * s, 2 * KTILE_W * 4);
            bulk_g2s(smaddr(Ks + s * KTILE_W), ksrc + (size_t)s * KTILE_W, KTILE_W * 4, mb0 + 8 * s);
            bulk_g2s(smaddr(Vs + s * KTILE_W), vsrc + (size_t)s * KTILE_W, KTILE_W * 4, mb0 + 8 * s);
        }
    }

    // Q fragments (fp16, pre-scaled, log2 domain)
    unsigned qa[4][4];
    {
        const unsigned* q0 = g_query_h + (size_t)(qb * 256 + w * 16 + grp) * 512 + h * 32;
        const unsigned* q1 = q0 + 8 * 512;
#pragma unroll
        for (int kb = 0; kb < 4; kb++) {
            qa[kb][0] = q0[kb * 8 + tig];
            qa[kb][1] = q1[kb * 8 + tig];
            qa[kb][2] = q0[kb * 8 + tig + 4];
            qa[kb][3] = q1[kb * 8 + tig + 4];
        }
    }

    float acc[8][4];
#pragma unroll
    for (int nt = 0; nt < 8; nt++)
#pragma unroll
        for (int i = 0; i < 4; i++) acc[nt][i] = 0.f;
    float m0 = -1e30f, m1 = -1e30f, l0 = 0.f, l1 = 0.f;

    for (int g = 0; g < AT_NT / 2; g++) {
#pragma unroll
        for (int sub = 0; sub < 2; sub++) {
            const int t = 2 * g + sub;
            const int s = t & 3;
            mbar_wait(mb0 + 8 * s, (unsigned)((t >> 2) & 1));

            const unsigned* Kc = Ks + s * KTILE_W;
            const unsigned* Vc = Vs + s * KTILE_W;

            // ---- S = Q K^T (log2 domain) ----
            float sc[8][4];
#pragma unroll
            for (int nt = 0; nt < 8; nt++)
#pragma unroll
                for (int i = 0; i < 4; i++) sc[nt][i] = 0.f;
#pragma unroll
            for (int kb = 0; kb < 4; kb++) {
#pragma unroll
                for (int nt = 0; nt < 8; nt++) {
                    const unsigned* Kp = Kc + (nt * 8 + grp) * KV_STR + kb * 8;
                    mma_f16(sc[nt], qa[kb], Kp[tig], Kp[tig + 4]);
                }
            }

            // ---- online softmax (fp16x2 exp2, P in registers) ----
            float mt0 = -1e30f, mt1 = -1e30f;
#pragma unroll
            for (int nt = 0; nt < 8; nt++) {
                mt0 = fmaxf(mt0, fmaxf(sc[nt][0], sc[nt][1]));
                mt1 = fmaxf(mt1, fmaxf(sc[nt][2], sc[nt][3]));
            }
            mt0 = fmaxf(mt0, __shfl_xor_sync(0xffffffff, mt0, 1));
            mt0 = fmaxf(mt0, __shfl_xor_sync(0xffffffff, mt0, 2));
            mt1 = fmaxf(mt1, __shfl_xor_sync(0xffffffff, mt1, 1));
            mt1 = fmaxf(mt1, __shfl_xor_sync(0xffffffff, mt1, 2));

            float mn0 = fmaxf(m0, mt0), mn1 = fmaxf(m1, mt1);
            float c0 = exp2f(m0 - mn0), c1 = exp2f(m1 - mn1);
            l0 *= c0; l1 *= c1;
            m0 = mn0; m1 = mn1;

            unsigned ph[8][2];
#pragma unroll
            for (int nt = 0; nt < 8; nt++) {
                ph[nt][0] = exp2_h2(sc[nt][0] - mn0, sc[nt][1] - mn0);
                ph[nt][1] = exp2_h2(sc[nt][2] - mn1, sc[nt][3] - mn1);
                acc[nt][0] *= c0; acc[nt][1] *= c0;
                acc[nt][2] *= c1; acc[nt][3] *= c1;
            }

            // l accumulation: HADD2 tree over nt, then to fp32
            {
                unsigned s00 = hadd2u(hadd2u(ph[0][0], ph[1][0]), hadd2u(ph[2][0], ph[3][0]));
                unsigned s01 = hadd2u(hadd2u(ph[4][0], ph[5][0]), hadd2u(ph[6][0], ph[7][0]));
                unsigned s10 = hadd2u(hadd2u(ph[0][1], ph[1][1]), hadd2u(ph[2][1], ph[3][1]));
                unsigned s11 = hadd2u(hadd2u(ph[4][1], ph[5][1]), hadd2u(ph[6][1], ph[7][1]));
                float2 f0 = __half22float2(*reinterpret_cast<__half2*>(&s00));
                float2 f1 = __half22float2(*reinterpret_cast<__half2*>(&s01));
                float2 f2 = __half22float2(*reinterpret_cast<__half2*>(&s10));
                float2 f3 = __half22float2(*reinterpret_cast<__half2*>(&s11));
                l0 += (f0.x + f0.y) + (f1.x + f1.y);
                l1 += (f2.x + f2.y) + (f3.x + f3.y);
            }

            // ---- acc += P @ V  (P a-frags direct from registers) ----
#pragma unroll
            for (int kb = 0; kb < 4; kb++) {
                unsigned a[4];
                a[0] = ph[2 * kb][0];
                a[1] = ph[2 * kb][1];
                a[2] = ph[2 * kb + 1][0];
                a[3] = ph[2 * kb + 1][1];
#pragma unroll
                for (int nt = 0; nt < 8; nt++) {
                    const unsigned* Vp = Vc + (nt * 8 + grp) * KV_STR + kb * 8;
                    mma_f16(acc[nt], a, Vp[tig], Vp[tig + 4]);
                }
            }
        }

        __syncthreads();
        if (tid == 0 && 2 * g + 4 < AT_NT) {
#pragma unroll
            for (int sub = 0; sub < 2; sub++) {
                const int t = 2 * g + 4 + sub;
                const int s = t & 3;
                mbar_expect(mb0 + 8 * s, 2 * KTILE_W * 4);
                bulk_g2s(smaddr(Ks + s * KTILE_W), ksrc + (size_t)t * KTILE_W, KTILE_W * 4, mb0 + 8 * s);
                bulk_g2s(smaddr(Vs + s * KTILE_W), vsrc + (size_t)t * KTILE_W, KTILE_W * 4, mb0 + 8 * s);
            }
        }
    }

    // ---- finalize: write fp16 XOR-swizzled A-tile layout for gemm_h<2> ----
    l0 += __shfl_xor_sync(0xffffffff, l0, 1);
    l0 += __shfl_xor_sync(0xffffffff, l0, 2);
    l1 += __shfl_xor_sync(0xffffffff, l1, 1);
    l1 += __shfl_xor_sync(0xffffffff, l1, 2);
    float inv0 = 1.f / l0, inv1 = 1.f / l1;

    int r0 = qb * 256 + w * 16 + grp;
    int r1 = r0 + 8;
#pragma unroll
    for (int nt = 0; nt < 8; nt++) {
        int col = h * HDIM + nt * 8 + 2 * tig;
        int kt = col >> 4;
        int wd = (col & 15) >> 1;
        {
            unsigned* base = g_attn_h + ((size_t)((r0 >> 7) * 64 + kt)) * GT_W + (r0 & 127) * 8;
            base[wd ^ (r0 & 7)] = f22h2(acc[nt][0] * inv0, acc[nt][1] * inv0);
        }
        {
            unsigned* base = g_attn_h + ((size_t)((r1 >> 7) * 64 + kt)) * GT_W + (r1 & 127) * 8;
            base[wd ^ (r1 & 7)] = f22h2(acc[nt][2] * inv1, acc[nt][3] * inv1);
        }
    }
}

// ---------------------------------------------------------------------------
extern "C" void kernel_launch(void* const* d_in, const int* in_sizes, int n_in,
                              void* d_out, int out_size)
{
    const float* utter = (const float*)d_in[0];
    const float* rctx  = (const float*)d_in[1];
    const float* mem   = (const float*)d_in[2];
    const float* lck   = (const float*)d_in[3];
    const float* lcv   = (const float*)d_in[4];
    const float* Wq    = (const float*)d_in[5];
    const float* bq    = (const float*)d_in[6];
    const float* Wkv   = (const float*)d_in[7];
    const float* bkv   = (const float*)d_in[8];
    const float* Wo    = (const float*)d_in[9];
    const float* bo    = (const float*)d_in[10];

    float* out = (float*)d_out;                       // [2304, 1024]
    float* key = out + (size_t)QLEN * D_DIM;          // [3840, 1024]
    float* val = key + (size_t)KVLEN * D_DIM;         // [3840, 1024]

    static cudaStream_t s1 = nullptr;
    static cudaEvent_t eFork = nullptr, eP1 = nullptr, eG1 = nullptr, eTail = nullptr;
    if (!s1) {
        cudaFuncSetAttribute(attn_mma, cudaFuncAttributeMaxDynamicSharedMemorySize, ATT_SMEM);
        cudaFuncSetAttribute(gemm_h<0>, cudaFuncAttributeMaxDynamicSharedMemorySize, GEMM_SMEM);
        cudaFuncSetAttribute(gemm_h<1>, cudaFuncAttributeMaxDynamicSharedMemorySize, GEMM_SMEM);
        cudaFuncSetAttribute(gemm_h<2>, cudaFuncAttributeMaxDynamicSharedMemorySize, GEMM_SMEM);
        cudaStreamCreateWithFlags(&s1, cudaStreamNonBlocking);
        cudaEventCreateWithFlags(&eFork, cudaEventDisableTiming);
        cudaEventCreateWithFlags(&eP1,   cudaEventDisableTiming);
        cudaEventCreateWithFlags(&eG1,   cudaEventDisableTiming);
        cudaEventCreateWithFlags(&eTail, cudaEventDisableTiming);
    }

    unsigned *wq_p, *wkv_p, *wo_p;
    cudaGetSymbolAddress((void**)&wq_p,  g_Wq_h);
    cudaGetSymbolAddress((void**)&wkv_p, g_Wkv_h);
    cudaGetSymbolAddress((void**)&wo_p,  g_Wo_h);

    // ---- fork s1 off the capture (legacy) stream ----
    cudaEventRecord(eFork, 0);
    cudaStreamWaitEvent(s1, eFork, 0);

    // ---- s0 chain: kvin -> Wq -> gemm0 (q proj) ----
    conv_kvin_h<<<512, 256, 0, 0>>>(utter, rctx, mem);
    cudaEventRecord(eP1, 0);                       // kvin ready
    conv_w_h<<<256, 256, 0, 0>>>(Wq, wq_p, D_DIM * D_DIM / 4);
    gemm_h<0><<<dim3(D_DIM / 128, QLEN / 128), 256, GEMM_SMEM, 0>>>(bq, nullptr, nullptr);

    // ---- s1 chain: Wkv -> lc -> (wait kvin) gemm1 -> Wo -> memcpys ----
    conv_w_h<<<512, 256, 0, s1>>>(Wkv, wkv_p, 2 * D_DIM * D_DIM / 4);
    conv_lc<<<256, 256, 0, s1>>>(lck, lcv);
    cudaStreamWaitEvent(s1, eP1, 0);
    gemm_h<1><<<dim3(2 * D_DIM / 128, KVIN / 128), 256, GEMM_SMEM, s1>>>(bkv, key, val);
    cudaEventRecord(eG1, s1);                      // kv + lc ready for attention
    conv_w_h<<<256, 256, 0, s1>>>(Wo, wo_p, D_DIM * D_DIM / 4);
    cudaMemcpyAsync(key + (size_t)MR * D_DIM, lck,
                    (size_t)L_LEN * D_DIM * sizeof(float),
                    cudaMemcpyDeviceToDevice, s1);
    cudaMemcpyAsync(val + (size_t)MR * D_DIM, lcv,
                    (size_t)L_LEN * D_DIM * sizeof(float),
                    cudaMemcpyDeviceToDevice, s1);
    cudaEventRecord(eTail, s1);                    // Wo + d_out splices done

    // ---- s0: attention (overlaps conv_wo + memcpys), then join + gemm2 ----
    cudaStreamWaitEvent(0, eG1, 0);
    attn_mma<<<dim3(NHEAD, QLEN / 256), 512, ATT_SMEM, 0>>>(0);
    cudaStreamWaitEvent(0, eTail, 0);              // join s1 back into capture stream
    gemm_h<2><<<dim3(D_DIM / 128, QLEN / 128), 256, GEMM_SMEM, 0>>>(bo, out, nullptr);
}